// round 1
// baseline (speedup 1.0000x reference)
#include <cuda_runtime.h>
#include <cstdint>

// ---------------------------------------------------------------------------
// Problem constants
// ---------------------------------------------------------------------------
#define B_SZ   2
#define T_SZ   2048
#define C_SZ   2048
#define NH     16
#define NKV    4
#define HD     128
#define KVD    (NKV*HD)      // 512
#define MROWS  (B_SZ*T_SZ)   // 4096

// Scratch buffers (allocation-free rule: __device__ globals)
__device__ float g_q[MROWS * C_SZ];
__device__ float g_k[MROWS * KVD];
__device__ float g_v[MROWS * KVD];
__device__ float g_y[MROWS * C_SZ];

#define DEV __device__ __forceinline__

DEV uint32_t f2tf(float f) {
    uint32_t u;
    asm("cvt.rna.tf32.f32 %0, %1;" : "=r"(u) : "f"(f));
    return u;
}

DEV void mma_tf32(float* d, const uint32_t* a, const uint32_t* b) {
    asm volatile(
        "mma.sync.aligned.m16n8k8.row.col.f32.tf32.tf32.f32 "
        "{%0,%1,%2,%3}, {%4,%5,%6,%7}, {%8,%9}, {%0,%1,%2,%3};\n"
        : "+f"(d[0]), "+f"(d[1]), "+f"(d[2]), "+f"(d[3])
        : "r"(a[0]), "r"(a[1]), "r"(a[2]), "r"(a[3]),
          "r"(b[0]), "r"(b[1]));
}

// ---------------------------------------------------------------------------
// NT GEMM: C[M,N] = A[M,K] * W[N,K]^T   (both row-major, K contiguous)
// tf32 mma, block tile 128x128x32, 8 warps (4x2), warp tile 32x64
// ---------------------------------------------------------------------------
#define BM 128
#define BN 128
#define BK 32

__global__ __launch_bounds__(256, 1)
void gemm_nt(const float* __restrict__ A, const float* __restrict__ W,
             float* __restrict__ C, int M, int N, int K) {
    __shared__ uint32_t sA[BM][BK + 4];
    __shared__ uint32_t sB[BN][BK + 4];

    const int tid  = threadIdx.x;
    const int warp = tid >> 5, lane = tid & 31;
    const int g = lane >> 2, tg = lane & 3;
    const int wm = (warp >> 1) * 32;   // warp row offset inside block
    const int wn = (warp & 1) * 64;    // warp col offset inside block
    const int m0 = blockIdx.y * BM, n0 = blockIdx.x * BN;

    float acc[2][8][4];
#pragma unroll
    for (int mf = 0; mf < 2; mf++)
#pragma unroll
        for (int nf = 0; nf < 8; nf++)
#pragma unroll
            for (int i = 0; i < 4; i++) acc[mf][nf][i] = 0.f;

    for (int k0 = 0; k0 < K; k0 += BK) {
        // Load A tile 128x32 (1024 float4, 4 per thread)
#pragma unroll
        for (int i = 0; i < 4; i++) {
            int f = tid + i * 256;
            int r = f >> 3, c = (f & 7) * 4;
            float4 v4 = *(const float4*)&A[(size_t)(m0 + r) * K + k0 + c];
            uint32_t* d = &sA[r][c];
            d[0] = f2tf(v4.x); d[1] = f2tf(v4.y); d[2] = f2tf(v4.z); d[3] = f2tf(v4.w);
        }
        // Load W tile 128x32
#pragma unroll
        for (int i = 0; i < 4; i++) {
            int f = tid + i * 256;
            int r = f >> 3, c = (f & 7) * 4;
            float4 v4 = *(const float4*)&W[(size_t)(n0 + r) * K + k0 + c];
            uint32_t* d = &sB[r][c];
            d[0] = f2tf(v4.x); d[1] = f2tf(v4.y); d[2] = f2tf(v4.z); d[3] = f2tf(v4.w);
        }
        __syncthreads();

#pragma unroll
        for (int kk = 0; kk < 4; kk++) {
            uint32_t a[2][4];
#pragma unroll
            for (int mf = 0; mf < 2; mf++) {
                int r = wm + mf * 16 + g;
                int kc = kk * 8 + tg;
                a[mf][0] = sA[r][kc];     a[mf][1] = sA[r + 8][kc];
                a[mf][2] = sA[r][kc + 4]; a[mf][3] = sA[r + 8][kc + 4];
            }
#pragma unroll
            for (int nf = 0; nf < 8; nf++) {
                int cn = wn + nf * 8 + g;
                int kc = kk * 8 + tg;
                uint32_t bb[2] = { sB[cn][kc], sB[cn][kc + 4] };
                mma_tf32(acc[0][nf], a[0], bb);
                mma_tf32(acc[1][nf], a[1], bb);
            }
        }
        __syncthreads();
    }

    // Epilogue
#pragma unroll
    for (int mf = 0; mf < 2; mf++) {
        int r0 = m0 + wm + mf * 16 + g;
#pragma unroll
        for (int nf = 0; nf < 8; nf++) {
            int c0 = n0 + wn + nf * 8 + 2 * tg;
            C[(size_t)r0 * N + c0]           = acc[mf][nf][0];
            C[(size_t)r0 * N + c0 + 1]       = acc[mf][nf][1];
            C[(size_t)(r0 + 8) * N + c0]     = acc[mf][nf][2];
            C[(size_t)(r0 + 8) * N + c0 + 1] = acc[mf][nf][3];
        }
    }
}

// ---------------------------------------------------------------------------
// Fused per-head RMSNorm + RoPE for q and k (in place).
// One warp per (row, head). Lane handles dims {l, l+32, l+64, l+96}.
// ---------------------------------------------------------------------------
__global__ void normrope(float* __restrict__ q, float* __restrict__ k) {
    int w = (blockIdx.x * blockDim.x + threadIdx.x) >> 5;
    int lane = threadIdx.x & 31;
    const int QW = MROWS * NH;
    float* base;
    int t;
    if (w < QW) {
        int row = w / NH, h = w % NH;
        base = q + (size_t)row * C_SZ + h * HD;
        t = row % T_SZ;
    } else {
        int w2 = w - QW;
        if (w2 >= MROWS * NKV) return;
        int row = w2 / NKV, h = w2 % NKV;
        base = k + (size_t)row * KVD + h * HD;
        t = row % T_SZ;
    }
    float x0 = base[lane], x1 = base[lane + 32], x2 = base[lane + 64], x3 = base[lane + 96];
    float ss = x0 * x0 + x1 * x1 + x2 * x2 + x3 * x3;
#pragma unroll
    for (int o = 16; o; o >>= 1) ss += __shfl_xor_sync(0xffffffffu, ss, o);
    float rn = rsqrtf(ss * (1.0f / 128.0f) + 1.1920928955078125e-7f);
    x0 *= rn; x1 *= rn; x2 *= rn; x3 *= rn;

    // inv_freq[i] = 10000^(-i/64), computed in double then rounded to f32
    const double LG = 9.210340371976184;   // ln(10000)
    float inv0 = (float)exp(-(double)lane * (LG / 64.0));
    float inv1 = (float)exp(-(double)(lane + 32) * (LG / 64.0));
    float tf = (float)t;
    float a0 = tf * inv0, a1 = tf * inv1;
    float c0 = cosf(a0), s0 = sinf(a0);
    float c1 = cosf(a1), s1 = sinf(a1);

    base[lane]      =  x0 * c0 + x2 * s0;
    base[lane + 64] = -x0 * s0 + x2 * c0;
    base[lane + 32] =  x1 * c1 + x3 * s1;
    base[lane + 96] = -x1 * s1 + x3 * c1;
}

// ---------------------------------------------------------------------------
// Flash attention, causal, GQA (group = 4). Br=128, Bc=64, D=128.
// 8 warps; warp w owns rows [16w, 16w+16). tf32 mma for QK^T and PV.
// ---------------------------------------------------------------------------
#define SQ_LD 132
#define SK_LD 132
#define SP_LD 68
#define OFF_Q 0
#define OFF_K (128 * SQ_LD)
#define OFF_V (OFF_K + 64 * SK_LD)
#define OFF_P (OFF_V + 64 * SK_LD)
#define ATTN_SMEM_WORDS (OFF_P + 128 * SP_LD)
#define ATTN_SMEM_BYTES (ATTN_SMEM_WORDS * 4)

__global__ __launch_bounds__(256, 1)
void attn_kernel(const float* __restrict__ q, const float* __restrict__ k,
                 const float* __restrict__ v, float* __restrict__ y) {
    extern __shared__ uint32_t sm[];
    uint32_t* sQ = sm + OFF_Q;   // [128][132]
    uint32_t* sK = sm + OFF_K;   // [64][132]
    uint32_t* sV = sm + OFF_V;   // [64][132]
    uint32_t* sP = sm + OFF_P;   // [128][68]

    const int tid = threadIdx.x, warp = tid >> 5, lane = tid & 31;
    const int g = lane >> 2, tg = lane & 3;
    const int q0 = blockIdx.x * 128;
    const int h = blockIdx.y, b = blockIdx.z;
    const int kvh = h >> 2;

    const float* qb = q + (size_t)b * T_SZ * C_SZ + (size_t)h * HD;
    const float* kb = k + (size_t)b * T_SZ * KVD + (size_t)kvh * HD;
    const float* vb = v + (size_t)b * T_SZ * KVD + (size_t)kvh * HD;
    float*       yb = y + (size_t)b * T_SZ * C_SZ + (size_t)h * HD;

    // Load Q tile (128 rows x 128 dims), tf32-converted
#pragma unroll
    for (int i = 0; i < 16; i++) {
        int f = tid + i * 256;           // float4 index, 0..4095
        int r = f >> 5, c = (f & 31) * 4;
        float4 v4 = *(const float4*)&qb[(size_t)(q0 + r) * C_SZ + c];
        uint32_t* d = &sQ[r * SQ_LD + c];
        d[0] = f2tf(v4.x); d[1] = f2tf(v4.y); d[2] = f2tf(v4.z); d[3] = f2tf(v4.w);
    }

    float oacc[16][4];
#pragma unroll
    for (int nf = 0; nf < 16; nf++)
#pragma unroll
        for (int i = 0; i < 4; i++) oacc[nf][i] = 0.f;
    float m0r = -1e30f, m1r = -1e30f, l0r = 0.f, l1r = 0.f;

    const int wr = warp * 16;
    const int ntiles = q0 / 64 + 2;
    const float scale = 0.08838834764831845f;   // 1/sqrt(128)

    for (int j = 0; j < ntiles; j++) {
        const int k0 = j * 64;
        __syncthreads();   // prior-iteration readers done before overwrite
        // Load K and V tiles (64 x 128 each)
#pragma unroll
        for (int i = 0; i < 8; i++) {
            int f = tid + i * 256;       // 0..2047
            int r = f >> 5, c = (f & 31) * 4;
            float4 k4 = *(const float4*)&kb[(size_t)(k0 + r) * KVD + c];
            uint32_t* dk = &sK[r * SK_LD + c];
            dk[0] = f2tf(k4.x); dk[1] = f2tf(k4.y); dk[2] = f2tf(k4.z); dk[3] = f2tf(k4.w);
            float4 v4 = *(const float4*)&vb[(size_t)(k0 + r) * KVD + c];
            uint32_t* dv = &sV[r * SK_LD + c];
            dv[0] = f2tf(v4.x); dv[1] = f2tf(v4.y); dv[2] = f2tf(v4.z); dv[3] = f2tf(v4.w);
        }
        __syncthreads();

        // S = Q K^T  (16 x 64 per warp)
        float sacc[8][4];
#pragma unroll
        for (int nf = 0; nf < 8; nf++)
#pragma unroll
            for (int i = 0; i < 4; i++) sacc[nf][i] = 0.f;

#pragma unroll
        for (int kk = 0; kk < 16; kk++) {
            const int kc = kk * 8 + tg;
            uint32_t a[4];
            a[0] = sQ[(wr + g) * SQ_LD + kc];
            a[1] = sQ[(wr + g + 8) * SQ_LD + kc];
            a[2] = sQ[(wr + g) * SQ_LD + kc + 4];
            a[3] = sQ[(wr + g + 8) * SQ_LD + kc + 4];
#pragma unroll
            for (int nf = 0; nf < 8; nf++) {
                int cn = nf * 8 + g;
                uint32_t bb[2] = { sK[cn * SK_LD + kc], sK[cn * SK_LD + kc + 4] };
                mma_tf32(sacc[nf], a, bb);
            }
        }

        // scale + causal mask
        const int qr0 = q0 + wr + g, qr1 = qr0 + 8;
        const bool need_mask = (k0 + 63 > q0 + wr);
#pragma unroll
        for (int nf = 0; nf < 8; nf++) {
            int key = k0 + nf * 8 + 2 * tg;
#pragma unroll
            for (int i = 0; i < 4; i++) {
                int kc = key + (i & 1);
                int qr = (i < 2) ? qr0 : qr1;
                float s = sacc[nf][i] * scale;
                if (need_mask && kc > qr) s = -1e30f;
                sacc[nf][i] = s;
            }
        }

        // online softmax (thread owns 2 rows: qr0, qr1)
        float mx0 = -1e30f, mx1 = -1e30f;
#pragma unroll
        for (int nf = 0; nf < 8; nf++) {
            mx0 = fmaxf(mx0, fmaxf(sacc[nf][0], sacc[nf][1]));
            mx1 = fmaxf(mx1, fmaxf(sacc[nf][2], sacc[nf][3]));
        }
        mx0 = fmaxf(mx0, __shfl_xor_sync(0xffffffffu, mx0, 1));
        mx0 = fmaxf(mx0, __shfl_xor_sync(0xffffffffu, mx0, 2));
        mx1 = fmaxf(mx1, __shfl_xor_sync(0xffffffffu, mx1, 1));
        mx1 = fmaxf(mx1, __shfl_xor_sync(0xffffffffu, mx1, 2));

        float mn0 = fmaxf(m0r, mx0), mn1 = fmaxf(m1r, mx1);
        float al0 = __expf(m0r - mn0), al1 = __expf(m1r - mn1);
        float su0 = 0.f, su1 = 0.f;
#pragma unroll
        for (int nf = 0; nf < 8; nf++) {
            float p0 = __expf(sacc[nf][0] - mn0);
            float p1 = __expf(sacc[nf][1] - mn0);
            float p2 = __expf(sacc[nf][2] - mn1);
            float p3 = __expf(sacc[nf][3] - mn1);
            sacc[nf][0] = p0; sacc[nf][1] = p1; sacc[nf][2] = p2; sacc[nf][3] = p3;
            su0 += p0 + p1; su1 += p2 + p3;
        }
        su0 += __shfl_xor_sync(0xffffffffu, su0, 1);
        su0 += __shfl_xor_sync(0xffffffffu, su0, 2);
        su1 += __shfl_xor_sync(0xffffffffu, su1, 1);
        su1 += __shfl_xor_sync(0xffffffffu, su1, 2);
        l0r = l0r * al0 + su0;  l1r = l1r * al1 + su1;
        m0r = mn0;              m1r = mn1;
#pragma unroll
        for (int nf = 0; nf < 16; nf++) {
            oacc[nf][0] *= al0; oacc[nf][1] *= al0;
            oacc[nf][2] *= al1; oacc[nf][3] *= al1;
        }

        // stage P (tf32) in warp-private smem rows
        const int pr = wr + g;
#pragma unroll
        for (int nf = 0; nf < 8; nf++) {
            int pc = nf * 8 + 2 * tg;
            sP[pr * SP_LD + pc]           = f2tf(sacc[nf][0]);
            sP[pr * SP_LD + pc + 1]       = f2tf(sacc[nf][1]);
            sP[(pr + 8) * SP_LD + pc]     = f2tf(sacc[nf][2]);
            sP[(pr + 8) * SP_LD + pc + 1] = f2tf(sacc[nf][3]);
        }
        __syncwarp();

        // O += P V   (16 x 128 per warp)
#pragma unroll
        for (int kf = 0; kf < 8; kf++) {
            const int kc = kf * 8 + tg;
            uint32_t a[4];
            a[0] = sP[(wr + g) * SP_LD + kc];
            a[1] = sP[(wr + g + 8) * SP_LD + kc];
            a[2] = sP[(wr + g) * SP_LD + kc + 4];
            a[3] = sP[(wr + g + 8) * SP_LD + kc + 4];
#pragma unroll
            for (int nf = 0; nf < 16; nf++) {
                int cn = nf * 8 + g;
                uint32_t bb[2] = { sV[kc * SK_LD + cn],
                                   sV[(kc + 4) * SK_LD + cn] };
                mma_tf32(oacc[nf], a, bb);
            }
        }
        __syncwarp();
    }

    // epilogue: O /= l, write to y  [row, h*128 + d]
    float il0 = 1.0f / l0r, il1 = 1.0f / l1r;
    const int r0 = q0 + wr + g, r1 = r0 + 8;
#pragma unroll
    for (int nf = 0; nf < 16; nf++) {
        int c = nf * 8 + 2 * tg;
        yb[(size_t)r0 * C_SZ + c]     = oacc[nf][0] * il0;
        yb[(size_t)r0 * C_SZ + c + 1] = oacc[nf][1] * il0;
        yb[(size_t)r1 * C_SZ + c]     = oacc[nf][2] * il1;
        yb[(size_t)r1 * C_SZ + c + 1] = oacc[nf][3] * il1;
    }
}

// ---------------------------------------------------------------------------
// Launch
// ---------------------------------------------------------------------------
extern "C" void kernel_launch(void* const* d_in, const int* in_sizes, int n_in,
                              void* d_out, int out_size) {
    const float* x  = (const float*)d_in[0];
    const float* Wq = (const float*)d_in[1];
    const float* Wk = (const float*)d_in[2];
    const float* Wv = (const float*)d_in[3];
    const float* Wo = (const float*)d_in[4];
    float* out = (float*)d_out;

    float *gq, *gk, *gv, *gy;
    cudaGetSymbolAddress((void**)&gq, g_q);
    cudaGetSymbolAddress((void**)&gk, g_k);
    cudaGetSymbolAddress((void**)&gv, g_v);
    cudaGetSymbolAddress((void**)&gy, g_y);

    cudaFuncSetAttribute(attn_kernel,
                         cudaFuncAttributeMaxDynamicSharedMemorySize,
                         ATTN_SMEM_BYTES);

    // QKV projections
    gemm_nt<<<dim3(C_SZ / BN, MROWS / BM), 256>>>(x, Wq, gq, MROWS, C_SZ, C_SZ);
    gemm_nt<<<dim3(KVD / BN, MROWS / BM), 256>>>(x, Wk, gk, MROWS, KVD, C_SZ);
    gemm_nt<<<dim3(KVD / BN, MROWS / BM), 256>>>(x, Wv, gv, MROWS, KVD, C_SZ);

    // RMSNorm + RoPE on q, k
    {
        int total_warps = MROWS * NH + MROWS * NKV;   // 81920
        int blocks = (total_warps + 7) / 8;           // 8 warps per block
        normrope<<<blocks, 256>>>(gq, gk);
    }

    // Flash attention
    attn_kernel<<<dim3(T_SZ / 128, NH, B_SZ), 256, ATTN_SMEM_BYTES>>>(gq, gk, gv, gy);

    // Output projection
    gemm_nt<<<dim3(C_SZ / BN, MROWS / BM), 256>>>(gy, Wo, out, MROWS, C_SZ, C_SZ);
}

// round 2
// speedup vs baseline: 1.4058x; 1.4058x over previous
#include <cuda_runtime.h>
#include <cstdint>

// ---------------------------------------------------------------------------
// Problem constants
// ---------------------------------------------------------------------------
#define B_SZ   2
#define T_SZ   2048
#define C_SZ   2048
#define NH     16
#define NKV    4
#define HD     128
#define KVD    (NKV*HD)      // 512
#define MROWS  (B_SZ*T_SZ)   // 4096

// Scratch buffers (allocation-free rule: __device__ globals)
__device__ float g_q[MROWS * C_SZ];
__device__ float g_k[MROWS * KVD];
__device__ float g_v[MROWS * KVD];
__device__ float g_y[MROWS * C_SZ];
__device__ float g_invf[64];

#define DEV __device__ __forceinline__

DEV uint32_t f2tf(float f) {
    uint32_t u;
    asm("cvt.rna.tf32.f32 %0, %1;" : "=r"(u) : "f"(f));
    return u;
}

DEV void mma_tf32(float* d, const uint32_t* a, const uint32_t* b) {
    asm volatile(
        "mma.sync.aligned.m16n8k8.row.col.f32.tf32.tf32.f32 "
        "{%0,%1,%2,%3}, {%4,%5,%6,%7}, {%8,%9}, {%0,%1,%2,%3};\n"
        : "+f"(d[0]), "+f"(d[1]), "+f"(d[2]), "+f"(d[3])
        : "r"(a[0]), "r"(a[1]), "r"(a[2]), "r"(a[3]),
          "r"(b[0]), "r"(b[1]));
}

// ---------------------------------------------------------------------------
// inv_freq table init (double-precision, identical numerics to round 1)
// ---------------------------------------------------------------------------
__global__ void init_invf() {
    int i = threadIdx.x;
    if (i < 64) {
        const double LG = 9.210340371976184;   // ln(10000)
        g_invf[i] = (float)exp(-(double)i * (LG / 64.0));
    }
}

// ---------------------------------------------------------------------------
// NT GEMM: C[M,N] = A[M,K] * W[N,K]^T  (both row-major, K contiguous)
// tf32 mma, block tile 128x128x32, 8 warps (4x2), warp tile 32x64.
// Register-staged double buffering: LDG(next) overlaps compute(cur).
// ---------------------------------------------------------------------------
#define BM 128
#define BN 128
#define BK 32
#define G_LD   (BK + 4)          // 36 words per row
#define G_TILE (BM * G_LD)       // 4608 words per buffer
#define GEMM_SMEM_BYTES (4 * G_TILE * 4)   // 2 bufs * (A+B) = 73728 B

__global__ __launch_bounds__(256, 2)
void gemm_nt(const float* __restrict__ A, const float* __restrict__ W,
             float* __restrict__ C, int M, int N, int K) {
    extern __shared__ uint32_t smg[];
    uint32_t* sAb = smg;                 // [2][128][36]
    uint32_t* sBb = smg + 2 * G_TILE;    // [2][128][36]

    const int tid  = threadIdx.x;
    const int warp = tid >> 5, lane = tid & 31;
    const int g = lane >> 2, tg = lane & 3;
    const int wm = (warp >> 1) * 32;
    const int wn = (warp & 1) * 64;
    const int m0 = blockIdx.y * BM, n0 = blockIdx.x * BN;

    // per-thread load coords (4 float4 each for A and W per tile)
    const int lr = tid >> 3;          // base row 0..31 (+32*i)
    const int lc = (tid & 7) * 4;     // col 0..28

    float acc[2][8][4];
#pragma unroll
    for (int mf = 0; mf < 2; mf++)
#pragma unroll
        for (int nf = 0; nf < 8; nf++)
#pragma unroll
            for (int i = 0; i < 4; i++) acc[mf][nf][i] = 0.f;

    float4 ra[4], rb[4];
    // prologue LDG for tile 0
#pragma unroll
    for (int i = 0; i < 4; i++) {
        int r = lr + i * 32;
        ra[i] = *(const float4*)&A[(size_t)(m0 + r) * K + lc];
        rb[i] = *(const float4*)&W[(size_t)(n0 + r) * K + lc];
    }

    int p = 0;
    for (int k0 = 0; k0 < K; k0 += BK) {
        // stage registers -> smem (tf32-converted)
        uint32_t* sA = sAb + p * G_TILE;
        uint32_t* sB = sBb + p * G_TILE;
#pragma unroll
        for (int i = 0; i < 4; i++) {
            int r = lr + i * 32;
            uint32_t* da = &sA[r * G_LD + lc];
            da[0] = f2tf(ra[i].x); da[1] = f2tf(ra[i].y);
            da[2] = f2tf(ra[i].z); da[3] = f2tf(ra[i].w);
            uint32_t* db = &sB[r * G_LD + lc];
            db[0] = f2tf(rb[i].x); db[1] = f2tf(rb[i].y);
            db[2] = f2tf(rb[i].z); db[3] = f2tf(rb[i].w);
        }
        __syncthreads();

        // prefetch next tile into registers (overlaps with mma below)
        if (k0 + BK < K) {
            const float* An = A + (size_t)m0 * K + k0 + BK;
            const float* Wn = W + (size_t)n0 * K + k0 + BK;
#pragma unroll
            for (int i = 0; i < 4; i++) {
                int r = lr + i * 32;
                ra[i] = *(const float4*)&An[(size_t)r * K + lc];
                rb[i] = *(const float4*)&Wn[(size_t)r * K + lc];
            }
        }

        // compute from smem buffer p
#pragma unroll
        for (int kk = 0; kk < 4; kk++) {
            const int kc = kk * 8 + tg;
            uint32_t a[2][4];
#pragma unroll
            for (int mf = 0; mf < 2; mf++) {
                int r = wm + mf * 16 + g;
                a[mf][0] = sA[r * G_LD + kc];
                a[mf][1] = sA[(r + 8) * G_LD + kc];
                a[mf][2] = sA[r * G_LD + kc + 4];
                a[mf][3] = sA[(r + 8) * G_LD + kc + 4];
            }
#pragma unroll
            for (int nf = 0; nf < 8; nf++) {
                int cn = wn + nf * 8 + g;
                uint32_t bb[2] = { sB[cn * G_LD + kc], sB[cn * G_LD + kc + 4] };
                mma_tf32(acc[0][nf], a[0], bb);
                mma_tf32(acc[1][nf], a[1], bb);
            }
        }
        p ^= 1;
    }

    // Epilogue
#pragma unroll
    for (int mf = 0; mf < 2; mf++) {
        int r0 = m0 + wm + mf * 16 + g;
#pragma unroll
        for (int nf = 0; nf < 8; nf++) {
            int c0 = n0 + wn + nf * 8 + 2 * tg;
            C[(size_t)r0 * N + c0]           = acc[mf][nf][0];
            C[(size_t)r0 * N + c0 + 1]       = acc[mf][nf][1];
            C[(size_t)(r0 + 8) * N + c0]     = acc[mf][nf][2];
            C[(size_t)(r0 + 8) * N + c0 + 1] = acc[mf][nf][3];
        }
    }
}

// ---------------------------------------------------------------------------
// Fused per-head RMSNorm + RoPE for q and k (in place).
// One warp per (row, head). Lane handles dims {l, l+32, l+64, l+96}.
// inv_freq read from precomputed table (no FP64 in hot path).
// ---------------------------------------------------------------------------
__global__ void normrope(float* __restrict__ q, float* __restrict__ k) {
    int w = (blockIdx.x * blockDim.x + threadIdx.x) >> 5;
    int lane = threadIdx.x & 31;
    const int QW = MROWS * NH;
    float* base;
    int t;
    if (w < QW) {
        int row = w / NH, h = w % NH;
        base = q + (size_t)row * C_SZ + h * HD;
        t = row % T_SZ;
    } else {
        int w2 = w - QW;
        if (w2 >= MROWS * NKV) return;
        int row = w2 / NKV, h = w2 % NKV;
        base = k + (size_t)row * KVD + h * HD;
        t = row % T_SZ;
    }
    float x0 = base[lane], x1 = base[lane + 32], x2 = base[lane + 64], x3 = base[lane + 96];
    float ss = x0 * x0 + x1 * x1 + x2 * x2 + x3 * x3;
#pragma unroll
    for (int o = 16; o; o >>= 1) ss += __shfl_xor_sync(0xffffffffu, ss, o);
    float rn = rsqrtf(ss * (1.0f / 128.0f) + 1.1920928955078125e-7f);
    x0 *= rn; x1 *= rn; x2 *= rn; x3 *= rn;

    float inv0 = g_invf[lane];
    float inv1 = g_invf[lane + 32];
    float tf = (float)t;
    float a0 = tf * inv0, a1 = tf * inv1;
    float c0 = cosf(a0), s0 = sinf(a0);
    float c1 = cosf(a1), s1 = sinf(a1);

    base[lane]      =  x0 * c0 + x2 * s0;
    base[lane + 64] = -x0 * s0 + x2 * c0;
    base[lane + 32] =  x1 * c1 + x3 * s1;
    base[lane + 96] = -x1 * s1 + x3 * c1;
}

// ---------------------------------------------------------------------------
// Flash attention, causal, GQA (group = 4). Br=128, Bc=64, D=128.
// 8 warps; warp w owns rows [16w, 16w+16). tf32 mma for QK^T and PV.
// ---------------------------------------------------------------------------
#define SQ_LD 132
#define SK_LD 132
#define SP_LD 68
#define OFF_Q 0
#define OFF_K (128 * SQ_LD)
#define OFF_V (OFF_K + 64 * SK_LD)
#define OFF_P (OFF_V + 64 * SK_LD)
#define ATTN_SMEM_WORDS (OFF_P + 128 * SP_LD)
#define ATTN_SMEM_BYTES (ATTN_SMEM_WORDS * 4)

__global__ __launch_bounds__(256, 1)
void attn_kernel(const float* __restrict__ q, const float* __restrict__ k,
                 const float* __restrict__ v, float* __restrict__ y) {
    extern __shared__ uint32_t sm[];
    uint32_t* sQ = sm + OFF_Q;   // [128][132]
    uint32_t* sK = sm + OFF_K;   // [64][132]
    uint32_t* sV = sm + OFF_V;   // [64][132]
    uint32_t* sP = sm + OFF_P;   // [128][68]

    const int tid = threadIdx.x, warp = tid >> 5, lane = tid & 31;
    const int g = lane >> 2, tg = lane & 3;
    const int q0 = blockIdx.x * 128;
    const int h = blockIdx.y, b = blockIdx.z;
    const int kvh = h >> 2;

    const float* qb = q + (size_t)b * T_SZ * C_SZ + (size_t)h * HD;
    const float* kb = k + (size_t)b * T_SZ * KVD + (size_t)kvh * HD;
    const float* vb = v + (size_t)b * T_SZ * KVD + (size_t)kvh * HD;
    float*       yb = y + (size_t)b * T_SZ * C_SZ + (size_t)h * HD;

    // Load Q tile (128 rows x 128 dims), tf32-converted
#pragma unroll
    for (int i = 0; i < 16; i++) {
        int f = tid + i * 256;           // float4 index, 0..4095
        int r = f >> 5, c = (f & 31) * 4;
        float4 v4 = *(const float4*)&qb[(size_t)(q0 + r) * C_SZ + c];
        uint32_t* d = &sQ[r * SQ_LD + c];
        d[0] = f2tf(v4.x); d[1] = f2tf(v4.y); d[2] = f2tf(v4.z); d[3] = f2tf(v4.w);
    }

    float oacc[16][4];
#pragma unroll
    for (int nf = 0; nf < 16; nf++)
#pragma unroll
        for (int i = 0; i < 4; i++) oacc[nf][i] = 0.f;
    float m0r = -1e30f, m1r = -1e30f, l0r = 0.f, l1r = 0.f;

    const int wr = warp * 16;
    const int ntiles = q0 / 64 + 2;
    const float scale = 0.08838834764831845f;   // 1/sqrt(128)

    for (int j = 0; j < ntiles; j++) {
        const int k0 = j * 64;
        __syncthreads();   // prior-iteration readers done before overwrite
        // Load K and V tiles (64 x 128 each)
#pragma unroll
        for (int i = 0; i < 8; i++) {
            int f = tid + i * 256;       // 0..2047
            int r = f >> 5, c = (f & 31) * 4;
            float4 k4 = *(const float4*)&kb[(size_t)(k0 + r) * KVD + c];
            uint32_t* dk = &sK[r * SK_LD + c];
            dk[0] = f2tf(k4.x); dk[1] = f2tf(k4.y); dk[2] = f2tf(k4.z); dk[3] = f2tf(k4.w);
            float4 v4 = *(const float4*)&vb[(size_t)(k0 + r) * KVD + c];
            uint32_t* dv = &sV[r * SK_LD + c];
            dv[0] = f2tf(v4.x); dv[1] = f2tf(v4.y); dv[2] = f2tf(v4.z); dv[3] = f2tf(v4.w);
        }
        __syncthreads();

        // S = Q K^T  (16 x 64 per warp)
        float sacc[8][4];
#pragma unroll
        for (int nf = 0; nf < 8; nf++)
#pragma unroll
            for (int i = 0; i < 4; i++) sacc[nf][i] = 0.f;

#pragma unroll
        for (int kk = 0; kk < 16; kk++) {
            const int kc = kk * 8 + tg;
            uint32_t a[4];
            a[0] = sQ[(wr + g) * SQ_LD + kc];
            a[1] = sQ[(wr + g + 8) * SQ_LD + kc];
            a[2] = sQ[(wr + g) * SQ_LD + kc + 4];
            a[3] = sQ[(wr + g + 8) * SQ_LD + kc + 4];
#pragma unroll
            for (int nf = 0; nf < 8; nf++) {
                int cn = nf * 8 + g;
                uint32_t bb[2] = { sK[cn * SK_LD + kc], sK[cn * SK_LD + kc + 4] };
                mma_tf32(sacc[nf], a, bb);
            }
        }

        // scale + causal mask
        const int qr0 = q0 + wr + g, qr1 = qr0 + 8;
        const bool need_mask = (k0 + 63 > q0 + wr);
#pragma unroll
        for (int nf = 0; nf < 8; nf++) {
            int key = k0 + nf * 8 + 2 * tg;
#pragma unroll
            for (int i = 0; i < 4; i++) {
                int kc = key + (i & 1);
                int qr = (i < 2) ? qr0 : qr1;
                float s = sacc[nf][i] * scale;
                if (need_mask && kc > qr) s = -1e30f;
                sacc[nf][i] = s;
            }
        }

        // online softmax (thread owns 2 rows: qr0, qr1)
        float mx0 = -1e30f, mx1 = -1e30f;
#pragma unroll
        for (int nf = 0; nf < 8; nf++) {
            mx0 = fmaxf(mx0, fmaxf(sacc[nf][0], sacc[nf][1]));
            mx1 = fmaxf(mx1, fmaxf(sacc[nf][2], sacc[nf][3]));
        }
        mx0 = fmaxf(mx0, __shfl_xor_sync(0xffffffffu, mx0, 1));
        mx0 = fmaxf(mx0, __shfl_xor_sync(0xffffffffu, mx0, 2));
        mx1 = fmaxf(mx1, __shfl_xor_sync(0xffffffffu, mx1, 1));
        mx1 = fmaxf(mx1, __shfl_xor_sync(0xffffffffu, mx1, 2));

        float mn0 = fmaxf(m0r, mx0), mn1 = fmaxf(m1r, mx1);
        float al0 = __expf(m0r - mn0), al1 = __expf(m1r - mn1);
        float su0 = 0.f, su1 = 0.f;
#pragma unroll
        for (int nf = 0; nf < 8; nf++) {
            float p0 = __expf(sacc[nf][0] - mn0);
            float p1 = __expf(sacc[nf][1] - mn0);
            float p2 = __expf(sacc[nf][2] - mn1);
            float p3 = __expf(sacc[nf][3] - mn1);
            sacc[nf][0] = p0; sacc[nf][1] = p1; sacc[nf][2] = p2; sacc[nf][3] = p3;
            su0 += p0 + p1; su1 += p2 + p3;
        }
        su0 += __shfl_xor_sync(0xffffffffu, su0, 1);
        su0 += __shfl_xor_sync(0xffffffffu, su0, 2);
        su1 += __shfl_xor_sync(0xffffffffu, su1, 1);
        su1 += __shfl_xor_sync(0xffffffffu, su1, 2);
        l0r = l0r * al0 + su0;  l1r = l1r * al1 + su1;
        m0r = mn0;              m1r = mn1;
#pragma unroll
        for (int nf = 0; nf < 16; nf++) {
            oacc[nf][0] *= al0; oacc[nf][1] *= al0;
            oacc[nf][2] *= al1; oacc[nf][3] *= al1;
        }

        // stage P (tf32) in warp-private smem rows
        const int pr = wr + g;
#pragma unroll
        for (int nf = 0; nf < 8; nf++) {
            int pc = nf * 8 + 2 * tg;
            sP[pr * SP_LD + pc]           = f2tf(sacc[nf][0]);
            sP[pr * SP_LD + pc + 1]       = f2tf(sacc[nf][1]);
            sP[(pr + 8) * SP_LD + pc]     = f2tf(sacc[nf][2]);
            sP[(pr + 8) * SP_LD + pc + 1] = f2tf(sacc[nf][3]);
        }
        __syncwarp();

        // O += P V   (16 x 128 per warp)
#pragma unroll
        for (int kf = 0; kf < 8; kf++) {
            const int kc = kf * 8 + tg;
            uint32_t a[4];
            a[0] = sP[(wr + g) * SP_LD + kc];
            a[1] = sP[(wr + g + 8) * SP_LD + kc];
            a[2] = sP[(wr + g) * SP_LD + kc + 4];
            a[3] = sP[(wr + g + 8) * SP_LD + kc + 4];
#pragma unroll
            for (int nf = 0; nf < 16; nf++) {
                int cn = nf * 8 + g;
                uint32_t bb[2] = { sV[kc * SK_LD + cn],
                                   sV[(kc + 4) * SK_LD + cn] };
                mma_tf32(oacc[nf], a, bb);
            }
        }
        __syncwarp();
    }

    // epilogue: O /= l, write to y  [row, h*128 + d]
    float il0 = 1.0f / l0r, il1 = 1.0f / l1r;
    const int r0 = q0 + wr + g, r1 = r0 + 8;
#pragma unroll
    for (int nf = 0; nf < 16; nf++) {
        int c = nf * 8 + 2 * tg;
        yb[(size_t)r0 * C_SZ + c]     = oacc[nf][0] * il0;
        yb[(size_t)r0 * C_SZ + c + 1] = oacc[nf][1] * il0;
        yb[(size_t)r1 * C_SZ + c]     = oacc[nf][2] * il1;
        yb[(size_t)r1 * C_SZ + c + 1] = oacc[nf][3] * il1;
    }
}

// ---------------------------------------------------------------------------
// Launch
// ---------------------------------------------------------------------------
extern "C" void kernel_launch(void* const* d_in, const int* in_sizes, int n_in,
                              void* d_out, int out_size) {
    const float* x  = (const float*)d_in[0];
    const float* Wq = (const float*)d_in[1];
    const float* Wk = (const float*)d_in[2];
    const float* Wv = (const float*)d_in[3];
    const float* Wo = (const float*)d_in[4];
    float* out = (float*)d_out;

    float *gq, *gk, *gv, *gy;
    cudaGetSymbolAddress((void**)&gq, g_q);
    cudaGetSymbolAddress((void**)&gk, g_k);
    cudaGetSymbolAddress((void**)&gv, g_v);
    cudaGetSymbolAddress((void**)&gy, g_y);

    cudaFuncSetAttribute(attn_kernel,
                         cudaFuncAttributeMaxDynamicSharedMemorySize,
                         ATTN_SMEM_BYTES);
    cudaFuncSetAttribute(gemm_nt,
                         cudaFuncAttributeMaxDynamicSharedMemorySize,
                         GEMM_SMEM_BYTES);

    // inv_freq table (cheap; keeps numerics identical to FP64 reference calc)
    init_invf<<<1, 64>>>();

    // QKV projections
    gemm_nt<<<dim3(C_SZ / BN, MROWS / BM), 256, GEMM_SMEM_BYTES>>>(x, Wq, gq, MROWS, C_SZ, C_SZ);
    gemm_nt<<<dim3(KVD / BN, MROWS / BM), 256, GEMM_SMEM_BYTES>>>(x, Wk, gk, MROWS, KVD, C_SZ);
    gemm_nt<<<dim3(KVD / BN, MROWS / BM), 256, GEMM_SMEM_BYTES>>>(x, Wv, gv, MROWS, KVD, C_SZ);

    // RMSNorm + RoPE on q, k
    {
        int total_warps = MROWS * NH + MROWS * NKV;   // 81920
        int blocks = (total_warps + 7) / 8;           // 8 warps per block
        normrope<<<blocks, 256>>>(gq, gk);
    }

    // Flash attention
    attn_kernel<<<dim3(T_SZ / 128, NH, B_SZ), 256, ATTN_SMEM_BYTES>>>(gq, gk, gv, gy);

    // Output projection
    gemm_nt<<<dim3(C_SZ / BN, MROWS / BM), 256, GEMM_SMEM_BYTES>>>(gy, Wo, out, MROWS, C_SZ, C_SZ);
}

// round 8
// speedup vs baseline: 1.6336x; 1.1620x over previous
#include <cuda_runtime.h>
#include <cstdint>

// ---------------------------------------------------------------------------
// Problem constants
// ---------------------------------------------------------------------------
#define B_SZ   2
#define T_SZ   2048
#define C_SZ   2048
#define NH     16
#define NKV    4
#define HD     128
#define KVD    (NKV*HD)      // 512
#define MROWS  (B_SZ*T_SZ)   // 4096

// Scratch buffers (allocation-free rule: __device__ globals)
__device__ float g_q[MROWS * C_SZ];
__device__ float g_k[MROWS * KVD];
__device__ float g_vt[KVD * MROWS];    // V transposed: [kv_dim][b*T]
__device__ float g_y[MROWS * C_SZ];
__device__ float g_invf[64];

#define DEV __device__ __forceinline__

DEV uint32_t f2tf(float f) {
    uint32_t u;
    asm("cvt.rna.tf32.f32 %0, %1;" : "=r"(u) : "f"(f));
    return u;
}

DEV void mma_tf32(float* d, const uint32_t* a, const uint32_t* b) {
    asm volatile(
        "mma.sync.aligned.m16n8k8.row.col.f32.tf32.tf32.f32 "
        "{%0,%1,%2,%3}, {%4,%5,%6,%7}, {%8,%9}, {%0,%1,%2,%3};\n"
        : "+f"(d[0]), "+f"(d[1]), "+f"(d[2]), "+f"(d[3])
        : "r"(a[0]), "r"(a[1]), "r"(a[2]), "r"(a[3]),
          "r"(b[0]), "r"(b[1]));
}

DEV uint32_t smem_u32(const void* p) {
    uint32_t a;
    asm("{ .reg .u64 t; cvta.to.shared.u64 t, %1; cvt.u32.u64 %0, t; }"
        : "=r"(a) : "l"(p));
    return a;
}

// ldmatrix x4 (b16 view of tf32 data — pure bit movement)
DEV void ldm4(uint32_t* r, uint32_t addr) {
    asm volatile("ldmatrix.sync.aligned.m8n8.x4.shared.b16 {%0,%1,%2,%3}, [%4];"
                 : "=r"(r[0]), "=r"(r[1]), "=r"(r[2]), "=r"(r[3]) : "r"(addr));
}

// A-fragment tile addressing: 16 rows x 8 f32-cols starting at `tile` (byte addr).
// r0=(rows0-7,k0-3) r1=(rows8-15,k0-3) r2=(rows0-7,k4-7) r3=(rows8-15,k4-7)
DEV uint32_t a_addr(uint32_t tile, uint32_t ldb) {
    int l = threadIdx.x & 31;
    return tile + (uint32_t)((l & 7) + ((l >> 3) & 1) * 8) * ldb
                + (uint32_t)(l >> 4) * 16;
}
// B-fragment tile addressing (storage [n][k]): 16 n-rows x 8 f32 k-cols.
// r0,r1 = b0,b1 for n-rows 0-7; r2,r3 = b0,b1 for n-rows 8-15.
DEV uint32_t b_addr(uint32_t tile, uint32_t ldb) {
    int l = threadIdx.x & 31;
    return tile + (uint32_t)((l & 7) + (l >> 4) * 8) * ldb
                + (uint32_t)((l >> 3) & 1) * 16;
}

// ---------------------------------------------------------------------------
// inv_freq table init (double-precision, identical numerics to round 1)
// ---------------------------------------------------------------------------
__global__ void init_invf() {
    int i = threadIdx.x;
    if (i < 64) {
        const double LG = 9.210340371976184;   // ln(10000)
        g_invf[i] = (float)exp(-(double)i * (LG / 64.0));
    }
}

// ---------------------------------------------------------------------------
// NT GEMM: C[M,N] = A[M,K] * W[N,K]^T  (tf32 mma + ldmatrix fragments)
// block tile 128x128x32, 8 warps (4x2), warp tile 32x64, reg double-buffered.
// blockIdx.z selects (W0,C0,normal) vs (W1,C1,transposed-epilogue) — used to
// fuse the K and V projections (V written transposed for attention).
// ---------------------------------------------------------------------------
#define BM 128
#define BN 128
#define BK 32
#define G_LD   (BK + 4)          // 36 words = 144 B (odd 16B-group count)
#define G_TILE (BM * G_LD)
#define GEMM_SMEM_BYTES (4 * G_TILE * 4)

__global__ __launch_bounds__(256, 2)
void gemm_nt(const float* __restrict__ A,
             const float* __restrict__ W0, const float* __restrict__ W1,
             float* __restrict__ C0, float* __restrict__ C1,
             int N, int K, int ldT) {
    extern __shared__ uint32_t smg[];
    uint32_t* sAb = smg;
    uint32_t* sBb = smg + 2 * G_TILE;

    const float* W = blockIdx.z ? W1 : W0;
    float* C       = blockIdx.z ? C1 : C0;
    const int transC = blockIdx.z ? 1 : 0;

    const int tid  = threadIdx.x;
    const int warp = tid >> 5, lane = tid & 31;
    const int g = lane >> 2, tg = lane & 3;
    const int wm = (warp >> 1) * 32;
    const int wn = (warp & 1) * 64;
    const int m0 = blockIdx.y * BM, n0 = blockIdx.x * BN;

    const int lr = tid >> 3;
    const int lc = (tid & 7) * 4;

    float acc[2][8][4];
#pragma unroll
    for (int mf = 0; mf < 2; mf++)
#pragma unroll
        for (int nf = 0; nf < 8; nf++)
#pragma unroll
            for (int i = 0; i < 4; i++) acc[mf][nf][i] = 0.f;

    float4 ra[4], rb[4];
#pragma unroll
    for (int i = 0; i < 4; i++) {
        int r = lr + i * 32;
        ra[i] = *(const float4*)&A[(size_t)(m0 + r) * K + lc];
        rb[i] = *(const float4*)&W[(size_t)(n0 + r) * K + lc];
    }

    int p = 0;
    for (int k0 = 0; k0 < K; k0 += BK) {
        uint32_t* sA = sAb + p * G_TILE;
        uint32_t* sB = sBb + p * G_TILE;
#pragma unroll
        for (int i = 0; i < 4; i++) {
            int r = lr + i * 32;
            uint32_t* da = &sA[r * G_LD + lc];
            da[0] = f2tf(ra[i].x); da[1] = f2tf(ra[i].y);
            da[2] = f2tf(ra[i].z); da[3] = f2tf(ra[i].w);
            uint32_t* db = &sB[r * G_LD + lc];
            db[0] = f2tf(rb[i].x); db[1] = f2tf(rb[i].y);
            db[2] = f2tf(rb[i].z); db[3] = f2tf(rb[i].w);
        }
        __syncthreads();

        if (k0 + BK < K) {
            const float* An = A + (size_t)m0 * K + k0 + BK;
            const float* Wn = W + (size_t)n0 * K + k0 + BK;
#pragma unroll
            for (int i = 0; i < 4; i++) {
                int r = lr + i * 32;
                ra[i] = *(const float4*)&An[(size_t)r * K + lc];
                rb[i] = *(const float4*)&Wn[(size_t)r * K + lc];
            }
        }

        const uint32_t sAbyte = smem_u32(sA);
        const uint32_t sBbyte = smem_u32(sB);
#pragma unroll
        for (int kk = 0; kk < 4; kk++) {
            uint32_t a0[4], a1[4];
            ldm4(a0, a_addr(sAbyte + (uint32_t)wm * (G_LD * 4) + kk * 32, G_LD * 4));
            ldm4(a1, a_addr(sAbyte + (uint32_t)(wm + 16) * (G_LD * 4) + kk * 32, G_LD * 4));
#pragma unroll
            for (int nfp = 0; nfp < 4; nfp++) {
                uint32_t b[4];
                ldm4(b, b_addr(sBbyte + (uint32_t)(wn + nfp * 16) * (G_LD * 4) + kk * 32,
                               G_LD * 4));
                mma_tf32(acc[0][2 * nfp],     a0, b);
                mma_tf32(acc[0][2 * nfp + 1], a0, b + 2);
                mma_tf32(acc[1][2 * nfp],     a1, b);
                mma_tf32(acc[1][2 * nfp + 1], a1, b + 2);
            }
        }
        __syncthreads();
        p ^= 1;
    }

    if (!transC) {
#pragma unroll
        for (int mf = 0; mf < 2; mf++) {
            int r0 = m0 + wm + mf * 16 + g;
#pragma unroll
            for (int nf = 0; nf < 8; nf++) {
                int c0 = n0 + wn + nf * 8 + 2 * tg;
                C[(size_t)r0 * N + c0]           = acc[mf][nf][0];
                C[(size_t)r0 * N + c0 + 1]       = acc[mf][nf][1];
                C[(size_t)(r0 + 8) * N + c0]     = acc[mf][nf][2];
                C[(size_t)(r0 + 8) * N + c0 + 1] = acc[mf][nf][3];
            }
        }
    } else {
        // transposed epilogue: Ct[n][m], ldT = MROWS
#pragma unroll
        for (int mf = 0; mf < 2; mf++) {
            int r0 = m0 + wm + mf * 16 + g;
#pragma unroll
            for (int nf = 0; nf < 8; nf++) {
                int c0 = n0 + wn + nf * 8 + 2 * tg;
                C[(size_t)c0 * ldT + r0]           = acc[mf][nf][0];
                C[(size_t)(c0 + 1) * ldT + r0]     = acc[mf][nf][1];
                C[(size_t)c0 * ldT + r0 + 8]       = acc[mf][nf][2];
                C[(size_t)(c0 + 1) * ldT + r0 + 8] = acc[mf][nf][3];
            }
        }
    }
}

// ---------------------------------------------------------------------------
// Fused per-head RMSNorm + RoPE for q and k (in place).
// ---------------------------------------------------------------------------
__global__ void normrope(float* __restrict__ q, float* __restrict__ k) {
    int w = (blockIdx.x * blockDim.x + threadIdx.x) >> 5;
    int lane = threadIdx.x & 31;
    const int QW = MROWS * NH;
    float* base;
    int t;
    if (w < QW) {
        int row = w / NH, h = w % NH;
        base = q + (size_t)row * C_SZ + h * HD;
        t = row % T_SZ;
    } else {
        int w2 = w - QW;
        if (w2 >= MROWS * NKV) return;
        int row = w2 / NKV, h = w2 % NKV;
        base = k + (size_t)row * KVD + h * HD;
        t = row % T_SZ;
    }
    float x0 = base[lane], x1 = base[lane + 32], x2 = base[lane + 64], x3 = base[lane + 96];
    float ss = x0 * x0 + x1 * x1 + x2 * x2 + x3 * x3;
#pragma unroll
    for (int o = 16; o; o >>= 1) ss += __shfl_xor_sync(0xffffffffu, ss, o);
    float rn = rsqrtf(ss * (1.0f / 128.0f) + 1.1920928955078125e-7f);
    x0 *= rn; x1 *= rn; x2 *= rn; x3 *= rn;

    float inv0 = g_invf[lane];
    float inv1 = g_invf[lane + 32];
    float tf = (float)t;
    float a0 = tf * inv0, a1 = tf * inv1;
    float c0 = cosf(a0), s0 = sinf(a0);
    float c1 = cosf(a1), s1 = sinf(a1);

    base[lane]      =  x0 * c0 + x2 * s0;
    base[lane + 64] = -x0 * s0 + x2 * c0;
    base[lane + 32] =  x1 * c1 + x3 * s1;
    base[lane + 96] = -x1 * s1 + x3 * c1;
}

// ---------------------------------------------------------------------------
// Flash attention, causal, GQA (group=4). Br=128, Bc=64, D=128.
// 8 warps; warp w owns rows [16w,16w+16). tf32 mma + ldmatrix fragments.
// V is consumed pre-transposed (g_vt[kv_dim][b*T]).
// ---------------------------------------------------------------------------
#define SQ_LD 132               // 528 B rows (33 groups of 16B, odd -> cf)
#define SVT_LD 68               // 272 B rows (17 groups, odd)
#define SP_LD 68
#define OFF_Q 0
#define OFF_K (128 * SQ_LD)
#define OFF_VT (OFF_K + 64 * SQ_LD)
#define OFF_P (OFF_VT + 128 * SVT_LD)
#define ATTN_SMEM_WORDS (OFF_P + 128 * SP_LD)
#define ATTN_SMEM_BYTES (ATTN_SMEM_WORDS * 4)

__global__ __launch_bounds__(256, 1)
void attn_kernel(const float* __restrict__ q, const float* __restrict__ k,
                 const float* __restrict__ vt, float* __restrict__ y) {
    extern __shared__ uint32_t sm[];
    uint32_t* sQ  = sm + OFF_Q;    // [128][132]
    uint32_t* sK  = sm + OFF_K;    // [64][132]
    uint32_t* sVt = sm + OFF_VT;   // [128 d][68 s]
    uint32_t* sP  = sm + OFF_P;    // [128][68]

    const int tid = threadIdx.x, warp = tid >> 5, lane = tid & 31;
    const int g = lane >> 2, tg = lane & 3;
    const int q0 = blockIdx.x * 128;
    const int h = blockIdx.y, b = blockIdx.z;
    const int kvh = h >> 2;

    const float* qb = q + (size_t)b * T_SZ * C_SZ + (size_t)h * HD;
    const float* kb = k + (size_t)b * T_SZ * KVD + (size_t)kvh * HD;
    const float* vbt = vt + (size_t)(kvh * HD) * MROWS + (size_t)b * T_SZ;
    float*       yb = y + (size_t)b * T_SZ * C_SZ + (size_t)h * HD;

    const uint32_t sQb  = smem_u32(sQ);
    const uint32_t sKb  = smem_u32(sK);
    const uint32_t sVtb = smem_u32(sVt);
    const uint32_t sPb  = smem_u32(sP);

    // Load Q tile (128 x 128), tf32-converted
#pragma unroll
    for (int i = 0; i < 16; i++) {
        int f = tid + i * 256;
        int r = f >> 5, c = (f & 31) * 4;
        float4 v4 = *(const float4*)&qb[(size_t)(q0 + r) * C_SZ + c];
        uint32_t* d = &sQ[r * SQ_LD + c];
        d[0] = f2tf(v4.x); d[1] = f2tf(v4.y); d[2] = f2tf(v4.z); d[3] = f2tf(v4.w);
    }

    float oacc[16][4];
#pragma unroll
    for (int nf = 0; nf < 16; nf++)
#pragma unroll
        for (int i = 0; i < 4; i++) oacc[nf][i] = 0.f;
    float m0r = -1e30f, m1r = -1e30f, l0r = 0.f, l1r = 0.f;

    const int wr = warp * 16;
    const int ntiles = q0 / 64 + 2;
    const float scale = 0.08838834764831845f;

    for (int j = 0; j < ntiles; j++) {
        const int k0 = j * 64;
        __syncthreads();
        // K tile: [64 s][128 d]
#pragma unroll
        for (int i = 0; i < 8; i++) {
            int f = tid + i * 256;
            int r = f >> 5, c = (f & 31) * 4;
            float4 k4 = *(const float4*)&kb[(size_t)(k0 + r) * KVD + c];
            uint32_t* dk = &sK[r * SQ_LD + c];
            dk[0] = f2tf(k4.x); dk[1] = f2tf(k4.y); dk[2] = f2tf(k4.z); dk[3] = f2tf(k4.w);
        }
        // Vt tile: [128 d][64 s]
#pragma unroll
        for (int i = 0; i < 8; i++) {
            int f = tid + i * 256;
            int r = f >> 4, c = (f & 15) * 4;
            float4 v4 = *(const float4*)&vbt[(size_t)r * MROWS + k0 + c];
            uint32_t* dv = &sVt[r * SVT_LD + c];
            dv[0] = f2tf(v4.x); dv[1] = f2tf(v4.y); dv[2] = f2tf(v4.z); dv[3] = f2tf(v4.w);
        }
        __syncthreads();

        // S = Q K^T (16 x 64 per warp)
        float sacc[8][4];
#pragma unroll
        for (int nf = 0; nf < 8; nf++)
#pragma unroll
            for (int i = 0; i < 4; i++) sacc[nf][i] = 0.f;

#pragma unroll
        for (int kk = 0; kk < 16; kk++) {
            uint32_t a[4];
            ldm4(a, a_addr(sQb + (uint32_t)wr * (SQ_LD * 4) + kk * 32, SQ_LD * 4));
#pragma unroll
            for (int nfp = 0; nfp < 4; nfp++) {
                uint32_t bfr[4];
                ldm4(bfr, b_addr(sKb + (uint32_t)(nfp * 16) * (SQ_LD * 4) + kk * 32,
                                 SQ_LD * 4));
                mma_tf32(sacc[2 * nfp],     a, bfr);
                mma_tf32(sacc[2 * nfp + 1], a, bfr + 2);
            }
        }

        // scale + causal mask
        const int qr0 = q0 + wr + g, qr1 = qr0 + 8;
        const bool need_mask = (k0 + 63 > q0 + wr);
#pragma unroll
        for (int nf = 0; nf < 8; nf++) {
            int key = k0 + nf * 8 + 2 * tg;
#pragma unroll
            for (int i = 0; i < 4; i++) {
                int kc = key + (i & 1);
                int qr = (i < 2) ? qr0 : qr1;
                float s = sacc[nf][i] * scale;
                if (need_mask && kc > qr) s = -1e30f;
                sacc[nf][i] = s;
            }
        }

        // online softmax
        float mx0 = -1e30f, mx1 = -1e30f;
#pragma unroll
        for (int nf = 0; nf < 8; nf++) {
            mx0 = fmaxf(mx0, fmaxf(sacc[nf][0], sacc[nf][1]));
            mx1 = fmaxf(mx1, fmaxf(sacc[nf][2], sacc[nf][3]));
        }
        mx0 = fmaxf(mx0, __shfl_xor_sync(0xffffffffu, mx0, 1));
        mx0 = fmaxf(mx0, __shfl_xor_sync(0xffffffffu, mx0, 2));
        mx1 = fmaxf(mx1, __shfl_xor_sync(0xffffffffu, mx1, 1));
        mx1 = fmaxf(mx1, __shfl_xor_sync(0xffffffffu, mx1, 2));

        float mn0 = fmaxf(m0r, mx0), mn1 = fmaxf(m1r, mx1);
        float al0 = __expf(m0r - mn0), al1 = __expf(m1r - mn1);
        float su0 = 0.f, su1 = 0.f;
#pragma unroll
        for (int nf = 0; nf < 8; nf++) {
            float p0 = __expf(sacc[nf][0] - mn0);
            float p1 = __expf(sacc[nf][1] - mn0);
            float p2 = __expf(sacc[nf][2] - mn1);
            float p3 = __expf(sacc[nf][3] - mn1);
            sacc[nf][0] = p0; sacc[nf][1] = p1; sacc[nf][2] = p2; sacc[nf][3] = p3;
            su0 += p0 + p1; su1 += p2 + p3;
        }
        su0 += __shfl_xor_sync(0xffffffffu, su0, 1);
        su0 += __shfl_xor_sync(0xffffffffu, su0, 2);
        su1 += __shfl_xor_sync(0xffffffffu, su1, 1);
        su1 += __shfl_xor_sync(0xffffffffu, su1, 2);
        l0r = l0r * al0 + su0;  l1r = l1r * al1 + su1;
        m0r = mn0;              m1r = mn1;
#pragma unroll
        for (int nf = 0; nf < 16; nf++) {
            oacc[nf][0] *= al0; oacc[nf][1] *= al0;
            oacc[nf][2] *= al1; oacc[nf][3] *= al1;
        }

        // stage P (tf32) in warp-private rows
        const int pr = wr + g;
#pragma unroll
        for (int nf = 0; nf < 8; nf++) {
            int pc = nf * 8 + 2 * tg;
            sP[pr * SP_LD + pc]           = f2tf(sacc[nf][0]);
            sP[pr * SP_LD + pc + 1]       = f2tf(sacc[nf][1]);
            sP[(pr + 8) * SP_LD + pc]     = f2tf(sacc[nf][2]);
            sP[(pr + 8) * SP_LD + pc + 1] = f2tf(sacc[nf][3]);
        }
        __syncwarp();

        // O += P * V  (A = P [16q x 8s], B = Vt [d][s] storage)
#pragma unroll
        for (int kf = 0; kf < 8; kf++) {
            uint32_t a[4];
            ldm4(a, a_addr(sPb + (uint32_t)wr * (SP_LD * 4) + kf * 32, SP_LD * 4));
#pragma unroll
            for (int nfp = 0; nfp < 8; nfp++) {
                uint32_t bfr[4];
                ldm4(bfr, b_addr(sVtb + (uint32_t)(nfp * 16) * (SVT_LD * 4) + kf * 32,
                                 SVT_LD * 4));
                mma_tf32(oacc[2 * nfp],     a, bfr);
                mma_tf32(oacc[2 * nfp + 1], a, bfr + 2);
            }
        }
        __syncwarp();
    }

    // epilogue
    float il0 = 1.0f / l0r, il1 = 1.0f / l1r;
    const int r0 = q0 + wr + g, r1 = r0 + 8;
#pragma unroll
    for (int nf = 0; nf < 16; nf++) {
        int c = nf * 8 + 2 * tg;
        yb[(size_t)r0 * C_SZ + c]     = oacc[nf][0] * il0;
        yb[(size_t)r0 * C_SZ + c + 1] = oacc[nf][1] * il0;
        yb[(size_t)r1 * C_SZ + c]     = oacc[nf][2] * il1;
        yb[(size_t)r1 * C_SZ + c + 1] = oacc[nf][3] * il1;
    }
}

// ---------------------------------------------------------------------------
// Launch
// ---------------------------------------------------------------------------
extern "C" void kernel_launch(void* const* d_in, const int* in_sizes, int n_in,
                              void* d_out, int out_size) {
    const float* x  = (const float*)d_in[0];
    const float* Wq = (const float*)d_in[1];
    const float* Wk = (const float*)d_in[2];
    const float* Wv = (const float*)d_in[3];
    const float* Wo = (const float*)d_in[4];
    float* out = (float*)d_out;

    float *gq, *gk, *gvt, *gy;
    cudaGetSymbolAddress((void**)&gq, g_q);
    cudaGetSymbolAddress((void**)&gk, g_k);
    cudaGetSymbolAddress((void**)&gvt, g_vt);
    cudaGetSymbolAddress((void**)&gy, g_y);

    cudaFuncSetAttribute(attn_kernel,
                         cudaFuncAttributeMaxDynamicSharedMemorySize,
                         ATTN_SMEM_BYTES);
    cudaFuncSetAttribute(gemm_nt,
                         cudaFuncAttributeMaxDynamicSharedMemorySize,
                         GEMM_SMEM_BYTES);

    init_invf<<<1, 64>>>();

    // Q projection
    gemm_nt<<<dim3(C_SZ / BN, MROWS / BM, 1), 256, GEMM_SMEM_BYTES>>>(
        x, Wq, Wq, gq, gq, C_SZ, C_SZ, 0);
    // K + V projections fused (z=0: K normal; z=1: V transposed epilogue)
    gemm_nt<<<dim3(KVD / BN, MROWS / BM, 2), 256, GEMM_SMEM_BYTES>>>(
        x, Wk, Wv, gk, gvt, KVD, C_SZ, MROWS);

    // RMSNorm + RoPE on q, k
    {
        int total_warps = MROWS * NH + MROWS * NKV;
        int blocks = (total_warps + 7) / 8;
        normrope<<<blocks, 256>>>(gq, gk);
    }

    // Flash attention
    attn_kernel<<<dim3(T_SZ / 128, NH, B_SZ), 256, ATTN_SMEM_BYTES>>>(gq, gk, gvt, gy);

    // Output projection
    gemm_nt<<<dim3(C_SZ / BN, MROWS / BM, 1), 256, GEMM_SMEM_BYTES>>>(
        gy, Wo, Wo, out, out, C_SZ, C_SZ, 0);
}

// round 11
// speedup vs baseline: 1.6478x; 1.0087x over previous
#include <cuda_runtime.h>
#include <cstdint>

// ---------------------------------------------------------------------------
// Problem constants
// ---------------------------------------------------------------------------
#define B_SZ   2
#define T_SZ   2048
#define C_SZ   2048
#define NH     16
#define NKV    4
#define HD     128
#define KVD    (NKV*HD)      // 512
#define MROWS  (B_SZ*T_SZ)   // 4096

// Scratch buffers (allocation-free rule: __device__ globals)
__device__ float g_q[MROWS * C_SZ];
__device__ float g_k[MROWS * KVD];
__device__ float g_vt[KVD * MROWS];    // V transposed: [kv_dim][b*T]
__device__ float g_y[MROWS * C_SZ];
__device__ float g_invf[64];
__device__ float2 g_cs[T_SZ * 64];     // rope cos/sin table

#define DEV __device__ __forceinline__

DEV uint32_t f2tf(float f) {
    uint32_t u;
    asm("cvt.rna.tf32.f32 %0, %1;" : "=r"(u) : "f"(f));
    return u;
}

DEV void mma_tf32(float* d, const uint32_t* a, const uint32_t* b) {
    asm volatile(
        "mma.sync.aligned.m16n8k8.row.col.f32.tf32.tf32.f32 "
        "{%0,%1,%2,%3}, {%4,%5,%6,%7}, {%8,%9}, {%0,%1,%2,%3};\n"
        : "+f"(d[0]), "+f"(d[1]), "+f"(d[2]), "+f"(d[3])
        : "r"(a[0]), "r"(a[1]), "r"(a[2]), "r"(a[3]),
          "r"(b[0]), "r"(b[1]));
}

DEV uint32_t smem_u32(const void* p) {
    uint32_t a;
    asm("{ .reg .u64 t; cvta.to.shared.u64 t, %1; cvt.u32.u64 %0, t; }"
        : "=r"(a) : "l"(p));
    return a;
}

// ldmatrix x4 (b16 view of tf32 data — pure bit movement)
DEV void ldm4(uint32_t* r, uint32_t addr) {
    asm volatile("ldmatrix.sync.aligned.m8n8.x4.shared.b16 {%0,%1,%2,%3}, [%4];"
                 : "=r"(r[0]), "=r"(r[1]), "=r"(r[2]), "=r"(r[3]) : "r"(addr));
}

// A-fragment tile addressing: 16 rows x 8 f32-cols starting at `tile` (byte addr).
DEV uint32_t a_addr(uint32_t tile, uint32_t ldb) {
    int l = threadIdx.x & 31;
    return tile + (uint32_t)((l & 7) + ((l >> 3) & 1) * 8) * ldb
                + (uint32_t)(l >> 4) * 16;
}
// B-fragment tile addressing (storage [n][k]): 16 n-rows x 8 f32 k-cols.
DEV uint32_t b_addr(uint32_t tile, uint32_t ldb) {
    int l = threadIdx.x & 31;
    return tile + (uint32_t)((l & 7) + (l >> 4) * 8) * ldb
                + (uint32_t)((l >> 3) & 1) * 16;
}

DEV void sts_v4(uint32_t addr, uint32_t x, uint32_t y, uint32_t z, uint32_t w) {
    asm volatile("st.shared.v4.b32 [%0], {%1,%2,%3,%4};"
                 :: "r"(addr), "r"(x), "r"(y), "r"(z), "r"(w) : "memory");
}

// ---------------------------------------------------------------------------
// init kernels: inv_freq (fp64, identical numerics) + rope cos/sin table
// ---------------------------------------------------------------------------
__global__ void init_invf() {
    int i = threadIdx.x;
    if (i < 64) {
        const double LG = 9.210340371976184;   // ln(10000)
        g_invf[i] = (float)exp(-(double)i * (LG / 64.0));
    }
}

__global__ void init_cs() {
    int t = blockIdx.x, i = threadIdx.x;   // 64 threads
    float a = (float)t * g_invf[i];        // identical expr to prior in-kernel calc
    g_cs[t * 64 + i] = make_float2(cosf(a), sinf(a));
}

// ---------------------------------------------------------------------------
// NT GEMM: C[M,N] = A[M,K] * W[N,K]^T  (tf32 mma + ldmatrix fragments)
// block tile 128x128x32, 8 warps (4x2), warp tile 32x64, reg double-buffered.
// blockIdx.z selects (W0,C0,normal) vs (W1,C1,transposed-epilogue).
// ---------------------------------------------------------------------------
#define BM 128
#define BN 128
#define BK 32
#define G_LD   (BK + 4)          // 36 words = 144 B (odd 16B-group count)
#define G_TILE (BM * G_LD)
#define GEMM_SMEM_BYTES (4 * G_TILE * 4)

__global__ __launch_bounds__(256, 2)
void gemm_nt(const float* __restrict__ A,
             const float* __restrict__ W0, const float* __restrict__ W1,
             float* __restrict__ C0, float* __restrict__ C1,
             int N, int K, int ldT) {
    extern __shared__ uint32_t smg[];
    uint32_t* sAb = smg;
    uint32_t* sBb = smg + 2 * G_TILE;

    const float* W = blockIdx.z ? W1 : W0;
    float* C       = blockIdx.z ? C1 : C0;
    const int transC = blockIdx.z ? 1 : 0;

    const int tid  = threadIdx.x;
    const int warp = tid >> 5, lane = tid & 31;
    const int g = lane >> 2, tg = lane & 3;
    const int wm = (warp >> 1) * 32;
    const int wn = (warp & 1) * 64;
    const int m0 = blockIdx.y * BM, n0 = blockIdx.x * BN;

    const int lr = tid >> 3;
    const int lc = (tid & 7) * 4;

    float acc[2][8][4];
#pragma unroll
    for (int mf = 0; mf < 2; mf++)
#pragma unroll
        for (int nf = 0; nf < 8; nf++)
#pragma unroll
            for (int i = 0; i < 4; i++) acc[mf][nf][i] = 0.f;

    float4 ra[4], rb[4];
#pragma unroll
    for (int i = 0; i < 4; i++) {
        int r = lr + i * 32;
        ra[i] = *(const float4*)&A[(size_t)(m0 + r) * K + lc];
        rb[i] = *(const float4*)&W[(size_t)(n0 + r) * K + lc];
    }

    int p = 0;
    for (int k0 = 0; k0 < K; k0 += BK) {
        uint32_t* sA = sAb + p * G_TILE;
        uint32_t* sB = sBb + p * G_TILE;
#pragma unroll
        for (int i = 0; i < 4; i++) {
            int r = lr + i * 32;
            uint32_t* da = &sA[r * G_LD + lc];
            da[0] = f2tf(ra[i].x); da[1] = f2tf(ra[i].y);
            da[2] = f2tf(ra[i].z); da[3] = f2tf(ra[i].w);
            uint32_t* db = &sB[r * G_LD + lc];
            db[0] = f2tf(rb[i].x); db[1] = f2tf(rb[i].y);
            db[2] = f2tf(rb[i].z); db[3] = f2tf(rb[i].w);
        }
        __syncthreads();

        if (k0 + BK < K) {
            const float* An = A + (size_t)m0 * K + k0 + BK;
            const float* Wn = W + (size_t)n0 * K + k0 + BK;
#pragma unroll
            for (int i = 0; i < 4; i++) {
                int r = lr + i * 32;
                ra[i] = *(const float4*)&An[(size_t)r * K + lc];
                rb[i] = *(const float4*)&Wn[(size_t)r * K + lc];
            }
        }

        const uint32_t sAbyte = smem_u32(sA);
        const uint32_t sBbyte = smem_u32(sB);
#pragma unroll
        for (int kk = 0; kk < 4; kk++) {
            uint32_t a0[4], a1[4];
            ldm4(a0, a_addr(sAbyte + (uint32_t)wm * (G_LD * 4) + kk * 32, G_LD * 4));
            ldm4(a1, a_addr(sAbyte + (uint32_t)(wm + 16) * (G_LD * 4) + kk * 32, G_LD * 4));
#pragma unroll
            for (int nfp = 0; nfp < 4; nfp++) {
                uint32_t b[4];
                ldm4(b, b_addr(sBbyte + (uint32_t)(wn + nfp * 16) * (G_LD * 4) + kk * 32,
                               G_LD * 4));
                mma_tf32(acc[0][2 * nfp],     a0, b);
                mma_tf32(acc[0][2 * nfp + 1], a0, b + 2);
                mma_tf32(acc[1][2 * nfp],     a1, b);
                mma_tf32(acc[1][2 * nfp + 1], a1, b + 2);
            }
        }
        __syncthreads();
        p ^= 1;
    }

    if (!transC) {
#pragma unroll
        for (int mf = 0; mf < 2; mf++) {
            int r0 = m0 + wm + mf * 16 + g;
#pragma unroll
            for (int nf = 0; nf < 8; nf++) {
                int c0 = n0 + wn + nf * 8 + 2 * tg;
                C[(size_t)r0 * N + c0]           = acc[mf][nf][0];
                C[(size_t)r0 * N + c0 + 1]       = acc[mf][nf][1];
                C[(size_t)(r0 + 8) * N + c0]     = acc[mf][nf][2];
                C[(size_t)(r0 + 8) * N + c0 + 1] = acc[mf][nf][3];
            }
        }
    } else {
        // transposed epilogue: Ct[n][m], ldT = MROWS
#pragma unroll
        for (int mf = 0; mf < 2; mf++) {
            int r0 = m0 + wm + mf * 16 + g;
#pragma unroll
            for (int nf = 0; nf < 8; nf++) {
                int c0 = n0 + wn + nf * 8 + 2 * tg;
                C[(size_t)c0 * ldT + r0]           = acc[mf][nf][0];
                C[(size_t)(c0 + 1) * ldT + r0]     = acc[mf][nf][1];
                C[(size_t)c0 * ldT + r0 + 8]       = acc[mf][nf][2];
                C[(size_t)(c0 + 1) * ldT + r0 + 8] = acc[mf][nf][3];
            }
        }
    }
}

// ---------------------------------------------------------------------------
// Fused per-head RMSNorm + RoPE for q and k (in place). cos/sin from table.
// ---------------------------------------------------------------------------
__global__ void normrope(float* __restrict__ q, float* __restrict__ k) {
    int w = (blockIdx.x * blockDim.x + threadIdx.x) >> 5;
    int lane = threadIdx.x & 31;
    const int QW = MROWS * NH;
    float* base;
    int t;
    if (w < QW) {
        int row = w / NH, h = w % NH;
        base = q + (size_t)row * C_SZ + h * HD;
        t = row % T_SZ;
    } else {
        int w2 = w - QW;
        if (w2 >= MROWS * NKV) return;
        int row = w2 / NKV, h = w2 % NKV;
        base = k + (size_t)row * KVD + h * HD;
        t = row % T_SZ;
    }
    float x0 = base[lane], x1 = base[lane + 32], x2 = base[lane + 64], x3 = base[lane + 96];
    float ss = x0 * x0 + x1 * x1 + x2 * x2 + x3 * x3;
#pragma unroll
    for (int o = 16; o; o >>= 1) ss += __shfl_xor_sync(0xffffffffu, ss, o);
    float rn = rsqrtf(ss * (1.0f / 128.0f) + 1.1920928955078125e-7f);
    x0 *= rn; x1 *= rn; x2 *= rn; x3 *= rn;

    float2 cs0 = g_cs[t * 64 + lane];
    float2 cs1 = g_cs[t * 64 + lane + 32];
    float c0 = cs0.x, s0 = cs0.y;
    float c1 = cs1.x, s1 = cs1.y;

    base[lane]      =  x0 * c0 + x2 * s0;
    base[lane + 64] = -x0 * s0 + x2 * c0;
    base[lane + 32] =  x1 * c1 + x3 * s1;
    base[lane + 96] = -x1 * s1 + x3 * c1;
}

// ---------------------------------------------------------------------------
// Flash attention, causal, GQA (group=4). Br=128, Bc=64, D=128.
// 8 warps; warp w owns rows [16w,16w+16). tf32 mma + ldmatrix fragments.
// V consumed pre-transposed. K/V double-buffered through registers so
// the next tile's LDGs overlap the current tile's compute.
// Block order reversed: longest (largest q0) causal blocks launch first.
// ---------------------------------------------------------------------------
#define SQ_LD 132               // 528 B rows (33 groups of 16B, odd -> cf)
#define SVT_LD 68               // 272 B rows (17 groups, odd)
#define SP_LD 68
#define OFF_Q 0
#define OFF_K (128 * SQ_LD)
#define OFF_VT (OFF_K + 64 * SQ_LD)
#define OFF_P (OFF_VT + 128 * SVT_LD)
#define ATTN_SMEM_WORDS (OFF_P + 128 * SP_LD)
#define ATTN_SMEM_BYTES (ATTN_SMEM_WORDS * 4)

__global__ __launch_bounds__(256, 1)
void attn_kernel(const float* __restrict__ q, const float* __restrict__ k,
                 const float* __restrict__ vt, float* __restrict__ y) {
    extern __shared__ uint32_t sm[];
    uint32_t* sQ  = sm + OFF_Q;    // [128][132]
    uint32_t* sK  = sm + OFF_K;    // [64][132]
    uint32_t* sVt = sm + OFF_VT;   // [128 d][68 s]
    uint32_t* sP  = sm + OFF_P;    // [128][68]

    const int tid = threadIdx.x, warp = tid >> 5, lane = tid & 31;
    const int g = lane >> 2, tg = lane & 3;
    const int q0 = (int)(gridDim.x - 1 - blockIdx.x) * 128;   // reversed order
    const int h = blockIdx.y, b = blockIdx.z;
    const int kvh = h >> 2;

    const float* qb = q + (size_t)b * T_SZ * C_SZ + (size_t)h * HD;
    const float* kb = k + (size_t)b * T_SZ * KVD + (size_t)kvh * HD;
    const float* vbt = vt + (size_t)(kvh * HD) * MROWS + (size_t)b * T_SZ;
    float*       yb = y + (size_t)b * T_SZ * C_SZ + (size_t)h * HD;

    const uint32_t sQb  = smem_u32(sQ);
    const uint32_t sKb  = smem_u32(sK);
    const uint32_t sVtb = smem_u32(sVt);
    const uint32_t sPb  = smem_u32(sP);

    // Prologue: issue LDGs for KV tile 0 into registers
    float4 rk[8], rv[8];
#pragma unroll
    for (int i = 0; i < 8; i++) {
        int f = tid + i * 256;
        int r = f >> 5, c = (f & 31) * 4;
        rk[i] = *(const float4*)&kb[(size_t)r * KVD + c];
    }
#pragma unroll
    for (int i = 0; i < 8; i++) {
        int f = tid + i * 256;
        int r = f >> 4, c = (f & 15) * 4;
        rv[i] = *(const float4*)&vbt[(size_t)r * MROWS + c];
    }

    // Load Q tile (128 x 128), tf32-converted
#pragma unroll
    for (int i = 0; i < 16; i++) {
        int f = tid + i * 256;
        int r = f >> 5, c = (f & 31) * 4;
        float4 v4 = *(const float4*)&qb[(size_t)(q0 + r) * C_SZ + c];
        uint32_t* d = &sQ[r * SQ_LD + c];
        d[0] = f2tf(v4.x); d[1] = f2tf(v4.y); d[2] = f2tf(v4.z); d[3] = f2tf(v4.w);
    }

    float oacc[16][4];
#pragma unroll
    for (int nf = 0; nf < 16; nf++)
#pragma unroll
        for (int i = 0; i < 4; i++) oacc[nf][i] = 0.f;
    float m0r = -1e30f, m1r = -1e30f, l0r = 0.f, l1r = 0.f;

    const int wr = warp * 16;
    const int ntiles = q0 / 64 + 2;
    const float scale = 0.08838834764831845f;

    for (int j = 0; j < ntiles; j++) {
        const int k0 = j * 64;
        __syncthreads();   // previous-iteration readers done before overwrite

        // stage registers -> smem (tf32 cvt, vectorized stores)
#pragma unroll
        for (int i = 0; i < 8; i++) {
            int f = tid + i * 256;
            int r = f >> 5, c = (f & 31) * 4;
            sts_v4(sKb + (uint32_t)(r * SQ_LD + c) * 4,
                   f2tf(rk[i].x), f2tf(rk[i].y), f2tf(rk[i].z), f2tf(rk[i].w));
        }
#pragma unroll
        for (int i = 0; i < 8; i++) {
            int f = tid + i * 256;
            int r = f >> 4, c = (f & 15) * 4;
            sts_v4(sVtb + (uint32_t)(r * SVT_LD + c) * 4,
                   f2tf(rv[i].x), f2tf(rv[i].y), f2tf(rv[i].z), f2tf(rv[i].w));
        }
        __syncthreads();

        // prefetch next KV tile into registers (overlaps with compute below)
        if (j + 1 < ntiles) {
            const int k0n = k0 + 64;
#pragma unroll
            for (int i = 0; i < 8; i++) {
                int f = tid + i * 256;
                int r = f >> 5, c = (f & 31) * 4;
                rk[i] = *(const float4*)&kb[(size_t)(k0n + r) * KVD + c];
            }
#pragma unroll
            for (int i = 0; i < 8; i++) {
                int f = tid + i * 256;
                int r = f >> 4, c = (f & 15) * 4;
                rv[i] = *(const float4*)&vbt[(size_t)r * MROWS + k0n + c];
            }
        }

        // S = Q K^T (16 x 64 per warp)
        float sacc[8][4];
#pragma unroll
        for (int nf = 0; nf < 8; nf++)
#pragma unroll
            for (int i = 0; i < 4; i++) sacc[nf][i] = 0.f;

#pragma unroll
        for (int kk = 0; kk < 16; kk++) {
            uint32_t a[4];
            ldm4(a, a_addr(sQb + (uint32_t)wr * (SQ_LD * 4) + kk * 32, SQ_LD * 4));
#pragma unroll
            for (int nfp = 0; nfp < 4; nfp++) {
                uint32_t bfr[4];
                ldm4(bfr, b_addr(sKb + (uint32_t)(nfp * 16) * (SQ_LD * 4) + kk * 32,
                                 SQ_LD * 4));
                mma_tf32(sacc[2 * nfp],     a, bfr);
                mma_tf32(sacc[2 * nfp + 1], a, bfr + 2);
            }
        }

        // scale + causal mask
        const int qr0 = q0 + wr + g, qr1 = qr0 + 8;
        const bool need_mask = (k0 + 63 > q0 + wr);
#pragma unroll
        for (int nf = 0; nf < 8; nf++) {
            int key = k0 + nf * 8 + 2 * tg;
#pragma unroll
            for (int i = 0; i < 4; i++) {
                int kc = key + (i & 1);
                int qr = (i < 2) ? qr0 : qr1;
                float s = sacc[nf][i] * scale;
                if (need_mask && kc > qr) s = -1e30f;
                sacc[nf][i] = s;
            }
        }

        // online softmax
        float mx0 = -1e30f, mx1 = -1e30f;
#pragma unroll
        for (int nf = 0; nf < 8; nf++) {
            mx0 = fmaxf(mx0, fmaxf(sacc[nf][0], sacc[nf][1]));
            mx1 = fmaxf(mx1, fmaxf(sacc[nf][2], sacc[nf][3]));
        }
        mx0 = fmaxf(mx0, __shfl_xor_sync(0xffffffffu, mx0, 1));
        mx0 = fmaxf(mx0, __shfl_xor_sync(0xffffffffu, mx0, 2));
        mx1 = fmaxf(mx1, __shfl_xor_sync(0xffffffffu, mx1, 1));
        mx1 = fmaxf(mx1, __shfl_xor_sync(0xffffffffu, mx1, 2));

        float mn0 = fmaxf(m0r, mx0), mn1 = fmaxf(m1r, mx1);
        float al0 = __expf(m0r - mn0), al1 = __expf(m1r - mn1);
        float su0 = 0.f, su1 = 0.f;
#pragma unroll
        for (int nf = 0; nf < 8; nf++) {
            float p0 = __expf(sacc[nf][0] - mn0);
            float p1 = __expf(sacc[nf][1] - mn0);
            float p2 = __expf(sacc[nf][2] - mn1);
            float p3 = __expf(sacc[nf][3] - mn1);
            sacc[nf][0] = p0; sacc[nf][1] = p1; sacc[nf][2] = p2; sacc[nf][3] = p3;
            su0 += p0 + p1; su1 += p2 + p3;
        }
        su0 += __shfl_xor_sync(0xffffffffu, su0, 1);
        su0 += __shfl_xor_sync(0xffffffffu, su0, 2);
        su1 += __shfl_xor_sync(0xffffffffu, su1, 1);
        su1 += __shfl_xor_sync(0xffffffffu, su1, 2);
        l0r = l0r * al0 + su0;  l1r = l1r * al1 + su1;
        m0r = mn0;              m1r = mn1;
#pragma unroll
        for (int nf = 0; nf < 16; nf++) {
            oacc[nf][0] *= al0; oacc[nf][1] *= al0;
            oacc[nf][2] *= al1; oacc[nf][3] *= al1;
        }

        // stage P (tf32) in warp-private rows
        const int pr = wr + g;
#pragma unroll
        for (int nf = 0; nf < 8; nf++) {
            int pc = nf * 8 + 2 * tg;
            sP[pr * SP_LD + pc]           = f2tf(sacc[nf][0]);
            sP[pr * SP_LD + pc + 1]       = f2tf(sacc[nf][1]);
            sP[(pr + 8) * SP_LD + pc]     = f2tf(sacc[nf][2]);
            sP[(pr + 8) * SP_LD + pc + 1] = f2tf(sacc[nf][3]);
        }
        __syncwarp();

        // O += P * V  (A = P [16q x 8s], B = Vt [d][s] storage)
#pragma unroll
        for (int kf = 0; kf < 8; kf++) {
            uint32_t a[4];
            ldm4(a, a_addr(sPb + (uint32_t)wr * (SP_LD * 4) + kf * 32, SP_LD * 4));
#pragma unroll
            for (int nfp = 0; nfp < 8; nfp++) {
                uint32_t bfr[4];
                ldm4(bfr, b_addr(sVtb + (uint32_t)(nfp * 16) * (SVT_LD * 4) + kf * 32,
                                 SVT_LD * 4));
                mma_tf32(oacc[2 * nfp],     a, bfr);
                mma_tf32(oacc[2 * nfp + 1], a, bfr + 2);
            }
        }
        __syncwarp();
    }

    // epilogue
    float il0 = 1.0f / l0r, il1 = 1.0f / l1r;
    const int r0 = q0 + wr + g, r1 = r0 + 8;
#pragma unroll
    for (int nf = 0; nf < 16; nf++) {
        int c = nf * 8 + 2 * tg;
        yb[(size_t)r0 * C_SZ + c]     = oacc[nf][0] * il0;
        yb[(size_t)r0 * C_SZ + c + 1] = oacc[nf][1] * il0;
        yb[(size_t)r1 * C_SZ + c]     = oacc[nf][2] * il1;
        yb[(size_t)r1 * C_SZ + c + 1] = oacc[nf][3] * il1;
    }
}

// ---------------------------------------------------------------------------
// Launch
// ---------------------------------------------------------------------------
extern "C" void kernel_launch(void* const* d_in, const int* in_sizes, int n_in,
                              void* d_out, int out_size) {
    const float* x  = (const float*)d_in[0];
    const float* Wq = (const float*)d_in[1];
    const float* Wk = (const float*)d_in[2];
    const float* Wv = (const float*)d_in[3];
    const float* Wo = (const float*)d_in[4];
    float* out = (float*)d_out;

    float *gq, *gk, *gvt, *gy;
    cudaGetSymbolAddress((void**)&gq, g_q);
    cudaGetSymbolAddress((void**)&gk, g_k);
    cudaGetSymbolAddress((void**)&gvt, g_vt);
    cudaGetSymbolAddress((void**)&gy, g_y);

    cudaFuncSetAttribute(attn_kernel,
                         cudaFuncAttributeMaxDynamicSharedMemorySize,
                         ATTN_SMEM_BYTES);
    cudaFuncSetAttribute(gemm_nt,
                         cudaFuncAttributeMaxDynamicSharedMemorySize,
                         GEMM_SMEM_BYTES);

    init_invf<<<1, 64>>>();
    init_cs<<<T_SZ, 64>>>();

    // Q projection
    gemm_nt<<<dim3(C_SZ / BN, MROWS / BM, 1), 256, GEMM_SMEM_BYTES>>>(
        x, Wq, Wq, gq, gq, C_SZ, C_SZ, 0);
    // K + V projections fused (z=0: K normal; z=1: V transposed epilogue)
    gemm_nt<<<dim3(KVD / BN, MROWS / BM, 2), 256, GEMM_SMEM_BYTES>>>(
        x, Wk, Wv, gk, gvt, KVD, C_SZ, MROWS);

    // RMSNorm + RoPE on q, k
    {
        int total_warps = MROWS * NH + MROWS * NKV;
        int blocks = (total_warps + 7) / 8;
        normrope<<<blocks, 256>>>(gq, gk);
    }

    // Flash attention
    attn_kernel<<<dim3(T_SZ / 128, NH, B_SZ), 256, ATTN_SMEM_BYTES>>>(gq, gk, gvt, gy);

    // Output projection
    gemm_nt<<<dim3(C_SZ / BN, MROWS / BM, 1), 256, GEMM_SMEM_BYTES>>>(
        gy, Wo, Wo, out, out, C_SZ, C_SZ, 0);
}

// round 12
// speedup vs baseline: 1.6906x; 1.0260x over previous
#include <cuda_runtime.h>
#include <cstdint>

// ---------------------------------------------------------------------------
// Problem constants
// ---------------------------------------------------------------------------
#define B_SZ   2
#define T_SZ   2048
#define C_SZ   2048
#define NH     16
#define NKV    4
#define HD     128
#define KVD    (NKV*HD)      // 512
#define MROWS  (B_SZ*T_SZ)   // 4096

// Scratch buffers (allocation-free rule: __device__ globals)
__device__ float g_q[MROWS * C_SZ];
__device__ float g_k[MROWS * KVD];
__device__ float g_vt[KVD * MROWS];    // V transposed: [kv_dim][b*T]
__device__ float g_y[MROWS * C_SZ];
__device__ float g_invf[64];
__device__ float2 g_cs[T_SZ * 64];     // rope cos/sin table

#define DEV __device__ __forceinline__

DEV uint32_t f2tf(float f) {
    uint32_t u;
    asm("cvt.rna.tf32.f32 %0, %1;" : "=r"(u) : "f"(f));
    return u;
}

DEV void mma_tf32(float* d, const uint32_t* a, const uint32_t* b) {
    asm volatile(
        "mma.sync.aligned.m16n8k8.row.col.f32.tf32.tf32.f32 "
        "{%0,%1,%2,%3}, {%4,%5,%6,%7}, {%8,%9}, {%0,%1,%2,%3};\n"
        : "+f"(d[0]), "+f"(d[1]), "+f"(d[2]), "+f"(d[3])
        : "r"(a[0]), "r"(a[1]), "r"(a[2]), "r"(a[3]),
          "r"(b[0]), "r"(b[1]));
}

DEV uint32_t smem_u32(const void* p) {
    uint32_t a;
    asm("{ .reg .u64 t; cvta.to.shared.u64 t, %1; cvt.u32.u64 %0, t; }"
        : "=r"(a) : "l"(p));
    return a;
}

// ldmatrix x4 (b16 view of tf32 data — pure bit movement)
DEV void ldm4(uint32_t* r, uint32_t addr) {
    asm volatile("ldmatrix.sync.aligned.m8n8.x4.shared.b16 {%0,%1,%2,%3}, [%4];"
                 : "=r"(r[0]), "=r"(r[1]), "=r"(r[2]), "=r"(r[3]) : "r"(addr));
}

// A-fragment tile addressing: 16 rows x 8 f32-cols starting at `tile` (byte addr).
DEV uint32_t a_addr(uint32_t tile, uint32_t ldb) {
    int l = threadIdx.x & 31;
    return tile + (uint32_t)((l & 7) + ((l >> 3) & 1) * 8) * ldb
                + (uint32_t)(l >> 4) * 16;
}
// B-fragment tile addressing (storage [n][k]): 16 n-rows x 8 f32 k-cols.
DEV uint32_t b_addr(uint32_t tile, uint32_t ldb) {
    int l = threadIdx.x & 31;
    return tile + (uint32_t)((l & 7) + (l >> 4) * 8) * ldb
                + (uint32_t)((l >> 3) & 1) * 16;
}

DEV void sts_v4(uint32_t addr, uint32_t x, uint32_t y, uint32_t z, uint32_t w) {
    asm volatile("st.shared.v4.b32 [%0], {%1,%2,%3,%4};"
                 :: "r"(addr), "r"(x), "r"(y), "r"(z), "r"(w) : "memory");
}

// ---------------------------------------------------------------------------
// init kernels: inv_freq (fp64, identical numerics) + rope cos/sin table
// ---------------------------------------------------------------------------
__global__ void init_invf() {
    int i = threadIdx.x;
    if (i < 64) {
        const double LG = 9.210340371976184;   // ln(10000)
        g_invf[i] = (float)exp(-(double)i * (LG / 64.0));
    }
}

__global__ void init_cs() {
    int t = blockIdx.x, i = threadIdx.x;   // 64 threads
    float a = (float)t * g_invf[i];        // identical expr to prior in-kernel calc
    g_cs[t * 64 + i] = make_float2(cosf(a), sinf(a));
}

// ---------------------------------------------------------------------------
// NT GEMM: C[M,N] = A[M,K] * W[N,K]^T  (tf32 mma + ldmatrix fragments)
// Block tile 256x128x32, 8 warps in 4x2 -> warp tile 64x64 (4.0 mma/LDSM).
// Register double-buffered staging. blockIdx.z selects (W0,C0,normal) vs
// (W1,C1,transposed-epilogue) to fuse the K and V projections.
// ---------------------------------------------------------------------------
#define BM 256
#define BN 128
#define BK 32
#define G_LD    (BK + 4)            // 36 words = 144 B (odd 16B-group count)
#define A_TILE  (BM * G_LD)         // words per A buffer
#define B_TILE  (BN * G_LD)         // words per B buffer
#define GEMM_SMEM_BYTES ((2 * A_TILE + 2 * B_TILE) * 4)   // 110592 B

__global__ __launch_bounds__(256, 1)
void gemm_nt(const float* __restrict__ A,
             const float* __restrict__ W0, const float* __restrict__ W1,
             float* __restrict__ C0, float* __restrict__ C1,
             int N, int K, int ldT) {
    extern __shared__ uint32_t smg[];
    uint32_t* sAb = smg;                    // [2][256][36]
    uint32_t* sBb = smg + 2 * A_TILE;       // [2][128][36]

    const float* W = blockIdx.z ? W1 : W0;
    float* C       = blockIdx.z ? C1 : C0;
    const int transC = blockIdx.z ? 1 : 0;

    const int tid  = threadIdx.x;
    const int warp = tid >> 5, lane = tid & 31;
    const int g = lane >> 2, tg = lane & 3;
    const int wm = (warp >> 1) * 64;        // 4 M-bands of 64
    const int wn = (warp & 1) * 64;         // 2 N-halves of 64
    const int m0 = blockIdx.y * BM, n0 = blockIdx.x * BN;

    const int lr = tid >> 3;                // 0..31
    const int lc = (tid & 7) * 4;           // 0..28

    float acc[4][8][4];
#pragma unroll
    for (int mi = 0; mi < 4; mi++)
#pragma unroll
        for (int nf = 0; nf < 8; nf++)
#pragma unroll
            for (int i = 0; i < 4; i++) acc[mi][nf][i] = 0.f;

    // staging registers: A 8 float4 (256 rows), B 4 float4 (128 rows)
    float4 ra[8], rb[4];
#pragma unroll
    for (int i = 0; i < 8; i++)
        ra[i] = *(const float4*)&A[(size_t)(m0 + lr + i * 32) * K + lc];
#pragma unroll
    for (int i = 0; i < 4; i++)
        rb[i] = *(const float4*)&W[(size_t)(n0 + lr + i * 32) * K + lc];

    int p = 0;
    for (int k0 = 0; k0 < K; k0 += BK) {
        uint32_t* sA = sAb + p * A_TILE;
        uint32_t* sB = sBb + p * B_TILE;
#pragma unroll
        for (int i = 0; i < 8; i++) {
            uint32_t* da = &sA[(lr + i * 32) * G_LD + lc];
            da[0] = f2tf(ra[i].x); da[1] = f2tf(ra[i].y);
            da[2] = f2tf(ra[i].z); da[3] = f2tf(ra[i].w);
        }
#pragma unroll
        for (int i = 0; i < 4; i++) {
            uint32_t* db = &sB[(lr + i * 32) * G_LD + lc];
            db[0] = f2tf(rb[i].x); db[1] = f2tf(rb[i].y);
            db[2] = f2tf(rb[i].z); db[3] = f2tf(rb[i].w);
        }
        __syncthreads();

        if (k0 + BK < K) {
            const float* An = A + (size_t)m0 * K + k0 + BK;
            const float* Wn = W + (size_t)n0 * K + k0 + BK;
#pragma unroll
            for (int i = 0; i < 8; i++)
                ra[i] = *(const float4*)&An[(size_t)(lr + i * 32) * K + lc];
#pragma unroll
            for (int i = 0; i < 4; i++)
                rb[i] = *(const float4*)&Wn[(size_t)(lr + i * 32) * K + lc];
        }

        const uint32_t sAbyte = smem_u32(sA);
        const uint32_t sBbyte = smem_u32(sB);
#pragma unroll
        for (int kk = 0; kk < 4; kk++) {
            uint32_t av[4][4];
#pragma unroll
            for (int mi = 0; mi < 4; mi++)
                ldm4(av[mi], a_addr(sAbyte + (uint32_t)(wm + 16 * mi) * (G_LD * 4)
                                    + kk * 32, G_LD * 4));
#pragma unroll
            for (int nfp = 0; nfp < 4; nfp++) {
                uint32_t b[4];
                ldm4(b, b_addr(sBbyte + (uint32_t)(wn + 16 * nfp) * (G_LD * 4)
                               + kk * 32, G_LD * 4));
#pragma unroll
                for (int mi = 0; mi < 4; mi++) {
                    mma_tf32(acc[mi][2 * nfp],     av[mi], b);
                    mma_tf32(acc[mi][2 * nfp + 1], av[mi], b + 2);
                }
            }
        }
        __syncthreads();
        p ^= 1;
    }

    if (!transC) {
#pragma unroll
        for (int mi = 0; mi < 4; mi++) {
            int r0 = m0 + wm + mi * 16 + g;
#pragma unroll
            for (int nf = 0; nf < 8; nf++) {
                int c0 = n0 + wn + nf * 8 + 2 * tg;
                C[(size_t)r0 * N + c0]           = acc[mi][nf][0];
                C[(size_t)r0 * N + c0 + 1]       = acc[mi][nf][1];
                C[(size_t)(r0 + 8) * N + c0]     = acc[mi][nf][2];
                C[(size_t)(r0 + 8) * N + c0 + 1] = acc[mi][nf][3];
            }
        }
    } else {
        // transposed epilogue: Ct[n][m], ldT = MROWS
#pragma unroll
        for (int mi = 0; mi < 4; mi++) {
            int r0 = m0 + wm + mi * 16 + g;
#pragma unroll
            for (int nf = 0; nf < 8; nf++) {
                int c0 = n0 + wn + nf * 8 + 2 * tg;
                C[(size_t)c0 * ldT + r0]           = acc[mi][nf][0];
                C[(size_t)(c0 + 1) * ldT + r0]     = acc[mi][nf][1];
                C[(size_t)c0 * ldT + r0 + 8]       = acc[mi][nf][2];
                C[(size_t)(c0 + 1) * ldT + r0 + 8] = acc[mi][nf][3];
            }
        }
    }
}

// ---------------------------------------------------------------------------
// Fused per-head RMSNorm + RoPE for q and k (in place). cos/sin from table.
// ---------------------------------------------------------------------------
__global__ void normrope(float* __restrict__ q, float* __restrict__ k) {
    int w = (blockIdx.x * blockDim.x + threadIdx.x) >> 5;
    int lane = threadIdx.x & 31;
    const int QW = MROWS * NH;
    float* base;
    int t;
    if (w < QW) {
        int row = w / NH, h = w % NH;
        base = q + (size_t)row * C_SZ + h * HD;
        t = row % T_SZ;
    } else {
        int w2 = w - QW;
        if (w2 >= MROWS * NKV) return;
        int row = w2 / NKV, h = w2 % NKV;
        base = k + (size_t)row * KVD + h * HD;
        t = row % T_SZ;
    }
    float x0 = base[lane], x1 = base[lane + 32], x2 = base[lane + 64], x3 = base[lane + 96];
    float ss = x0 * x0 + x1 * x1 + x2 * x2 + x3 * x3;
#pragma unroll
    for (int o = 16; o; o >>= 1) ss += __shfl_xor_sync(0xffffffffu, ss, o);
    float rn = rsqrtf(ss * (1.0f / 128.0f) + 1.1920928955078125e-7f);
    x0 *= rn; x1 *= rn; x2 *= rn; x3 *= rn;

    float2 cs0 = g_cs[t * 64 + lane];
    float2 cs1 = g_cs[t * 64 + lane + 32];
    float c0 = cs0.x, s0 = cs0.y;
    float c1 = cs1.x, s1 = cs1.y;

    base[lane]      =  x0 * c0 + x2 * s0;
    base[lane + 64] = -x0 * s0 + x2 * c0;
    base[lane + 32] =  x1 * c1 + x3 * s1;
    base[lane + 96] = -x1 * s1 + x3 * c1;
}

// ---------------------------------------------------------------------------
// Flash attention, causal, GQA (group=4). Br=128, Bc=64, D=128.
// 8 warps; warp w owns rows [16w,16w+16). tf32 mma + ldmatrix fragments.
// V consumed pre-transposed. K/V double-buffered through registers.
// Block order reversed: longest (largest q0) causal blocks launch first.
// ---------------------------------------------------------------------------
#define SQ_LD 132               // 528 B rows (33 groups of 16B, odd -> cf)
#define SVT_LD 68               // 272 B rows (17 groups, odd)
#define SP_LD 68
#define OFF_Q 0
#define OFF_K (128 * SQ_LD)
#define OFF_VT (OFF_K + 64 * SQ_LD)
#define OFF_P (OFF_VT + 128 * SVT_LD)
#define ATTN_SMEM_WORDS (OFF_P + 128 * SP_LD)
#define ATTN_SMEM_BYTES (ATTN_SMEM_WORDS * 4)

__global__ __launch_bounds__(256, 1)
void attn_kernel(const float* __restrict__ q, const float* __restrict__ k,
                 const float* __restrict__ vt, float* __restrict__ y) {
    extern __shared__ uint32_t sm[];
    uint32_t* sQ  = sm + OFF_Q;    // [128][132]
    uint32_t* sK  = sm + OFF_K;    // [64][132]
    uint32_t* sVt = sm + OFF_VT;   // [128 d][68 s]
    uint32_t* sP  = sm + OFF_P;    // [128][68]

    const int tid = threadIdx.x, warp = tid >> 5, lane = tid & 31;
    const int g = lane >> 2, tg = lane & 3;
    const int q0 = (int)(gridDim.x - 1 - blockIdx.x) * 128;   // reversed order
    const int h = blockIdx.y, b = blockIdx.z;
    const int kvh = h >> 2;

    const float* qb = q + (size_t)b * T_SZ * C_SZ + (size_t)h * HD;
    const float* kb = k + (size_t)b * T_SZ * KVD + (size_t)kvh * HD;
    const float* vbt = vt + (size_t)(kvh * HD) * MROWS + (size_t)b * T_SZ;
    float*       yb = y + (size_t)b * T_SZ * C_SZ + (size_t)h * HD;

    const uint32_t sQb  = smem_u32(sQ);
    const uint32_t sKb  = smem_u32(sK);
    const uint32_t sVtb = smem_u32(sVt);
    const uint32_t sPb  = smem_u32(sP);

    // Prologue: issue LDGs for KV tile 0 into registers
    float4 rk[8], rv[8];
#pragma unroll
    for (int i = 0; i < 8; i++) {
        int f = tid + i * 256;
        int r = f >> 5, c = (f & 31) * 4;
        rk[i] = *(const float4*)&kb[(size_t)r * KVD + c];
    }
#pragma unroll
    for (int i = 0; i < 8; i++) {
        int f = tid + i * 256;
        int r = f >> 4, c = (f & 15) * 4;
        rv[i] = *(const float4*)&vbt[(size_t)r * MROWS + c];
    }

    // Load Q tile (128 x 128), tf32-converted
#pragma unroll
    for (int i = 0; i < 16; i++) {
        int f = tid + i * 256;
        int r = f >> 5, c = (f & 31) * 4;
        float4 v4 = *(const float4*)&qb[(size_t)(q0 + r) * C_SZ + c];
        uint32_t* d = &sQ[r * SQ_LD + c];
        d[0] = f2tf(v4.x); d[1] = f2tf(v4.y); d[2] = f2tf(v4.z); d[3] = f2tf(v4.w);
    }

    float oacc[16][4];
#pragma unroll
    for (int nf = 0; nf < 16; nf++)
#pragma unroll
        for (int i = 0; i < 4; i++) oacc[nf][i] = 0.f;
    float m0r = -1e30f, m1r = -1e30f, l0r = 0.f, l1r = 0.f;

    const int wr = warp * 16;
    const int ntiles = q0 / 64 + 2;
    const float scale = 0.08838834764831845f;

    for (int j = 0; j < ntiles; j++) {
        const int k0 = j * 64;
        __syncthreads();   // previous-iteration readers done before overwrite

        // stage registers -> smem (tf32 cvt, vectorized stores)
#pragma unroll
        for (int i = 0; i < 8; i++) {
            int f = tid + i * 256;
            int r = f >> 5, c = (f & 31) * 4;
            sts_v4(sKb + (uint32_t)(r * SQ_LD + c) * 4,
                   f2tf(rk[i].x), f2tf(rk[i].y), f2tf(rk[i].z), f2tf(rk[i].w));
        }
#pragma unroll
        for (int i = 0; i < 8; i++) {
            int f = tid + i * 256;
            int r = f >> 4, c = (f & 15) * 4;
            sts_v4(sVtb + (uint32_t)(r * SVT_LD + c) * 4,
                   f2tf(rv[i].x), f2tf(rv[i].y), f2tf(rv[i].z), f2tf(rv[i].w));
        }
        __syncthreads();

        // prefetch next KV tile into registers (overlaps with compute below)
        if (j + 1 < ntiles) {
            const int k0n = k0 + 64;
#pragma unroll
            for (int i = 0; i < 8; i++) {
                int f = tid + i * 256;
                int r = f >> 5, c = (f & 31) * 4;
                rk[i] = *(const float4*)&kb[(size_t)(k0n + r) * KVD + c];
            }
#pragma unroll
            for (int i = 0; i < 8; i++) {
                int f = tid + i * 256;
                int r = f >> 4, c = (f & 15) * 4;
                rv[i] = *(const float4*)&vbt[(size_t)r * MROWS + k0n + c];
            }
        }

        // S = Q K^T (16 x 64 per warp)
        float sacc[8][4];
#pragma unroll
        for (int nf = 0; nf < 8; nf++)
#pragma unroll
            for (int i = 0; i < 4; i++) sacc[nf][i] = 0.f;

#pragma unroll
        for (int kk = 0; kk < 16; kk++) {
            uint32_t a[4];
            ldm4(a, a_addr(sQb + (uint32_t)wr * (SQ_LD * 4) + kk * 32, SQ_LD * 4));
#pragma unroll
            for (int nfp = 0; nfp < 4; nfp++) {
                uint32_t bfr[4];
                ldm4(bfr, b_addr(sKb + (uint32_t)(nfp * 16) * (SQ_LD * 4) + kk * 32,
                                 SQ_LD * 4));
                mma_tf32(sacc[2 * nfp],     a, bfr);
                mma_tf32(sacc[2 * nfp + 1], a, bfr + 2);
            }
        }

        // scale + causal mask
        const int qr0 = q0 + wr + g, qr1 = qr0 + 8;
        const bool need_mask = (k0 + 63 > q0 + wr);
#pragma unroll
        for (int nf = 0; nf < 8; nf++) {
            int key = k0 + nf * 8 + 2 * tg;
#pragma unroll
            for (int i = 0; i < 4; i++) {
                int kc = key + (i & 1);
                int qr = (i < 2) ? qr0 : qr1;
                float s = sacc[nf][i] * scale;
                if (need_mask && kc > qr) s = -1e30f;
                sacc[nf][i] = s;
            }
        }

        // online softmax
        float mx0 = -1e30f, mx1 = -1e30f;
#pragma unroll
        for (int nf = 0; nf < 8; nf++) {
            mx0 = fmaxf(mx0, fmaxf(sacc[nf][0], sacc[nf][1]));
            mx1 = fmaxf(mx1, fmaxf(sacc[nf][2], sacc[nf][3]));
        }
        mx0 = fmaxf(mx0, __shfl_xor_sync(0xffffffffu, mx0, 1));
        mx0 = fmaxf(mx0, __shfl_xor_sync(0xffffffffu, mx0, 2));
        mx1 = fmaxf(mx1, __shfl_xor_sync(0xffffffffu, mx1, 1));
        mx1 = fmaxf(mx1, __shfl_xor_sync(0xffffffffu, mx1, 2));

        float mn0 = fmaxf(m0r, mx0), mn1 = fmaxf(m1r, mx1);
        float al0 = __expf(m0r - mn0), al1 = __expf(m1r - mn1);
        float su0 = 0.f, su1 = 0.f;
#pragma unroll
        for (int nf = 0; nf < 8; nf++) {
            float p0 = __expf(sacc[nf][0] - mn0);
            float p1 = __expf(sacc[nf][1] - mn0);
            float p2 = __expf(sacc[nf][2] - mn1);
            float p3 = __expf(sacc[nf][3] - mn1);
            sacc[nf][0] = p0; sacc[nf][1] = p1; sacc[nf][2] = p2; sacc[nf][3] = p3;
            su0 += p0 + p1; su1 += p2 + p3;
        }
        su0 += __shfl_xor_sync(0xffffffffu, su0, 1);
        su0 += __shfl_xor_sync(0xffffffffu, su0, 2);
        su1 += __shfl_xor_sync(0xffffffffu, su1, 1);
        su1 += __shfl_xor_sync(0xffffffffu, su1, 2);
        l0r = l0r * al0 + su0;  l1r = l1r * al1 + su1;
        m0r = mn0;              m1r = mn1;
#pragma unroll
        for (int nf = 0; nf < 16; nf++) {
            oacc[nf][0] *= al0; oacc[nf][1] *= al0;
            oacc[nf][2] *= al1; oacc[nf][3] *= al1;
        }

        // stage P (tf32) in warp-private rows
        const int pr = wr + g;
#pragma unroll
        for (int nf = 0; nf < 8; nf++) {
            int pc = nf * 8 + 2 * tg;
            sP[pr * SP_LD + pc]           = f2tf(sacc[nf][0]);
            sP[pr * SP_LD + pc + 1]       = f2tf(sacc[nf][1]);
            sP[(pr + 8) * SP_LD + pc]     = f2tf(sacc[nf][2]);
            sP[(pr + 8) * SP_LD + pc + 1] = f2tf(sacc[nf][3]);
        }
        __syncwarp();

        // O += P * V  (A = P [16q x 8s], B = Vt [d][s] storage)
#pragma unroll
        for (int kf = 0; kf < 8; kf++) {
            uint32_t a[4];
            ldm4(a, a_addr(sPb + (uint32_t)wr * (SP_LD * 4) + kf * 32, SP_LD * 4));
#pragma unroll
            for (int nfp = 0; nfp < 8; nfp++) {
                uint32_t bfr[4];
                ldm4(bfr, b_addr(sVtb + (uint32_t)(nfp * 16) * (SVT_LD * 4) + kf * 32,
                                 SVT_LD * 4));
                mma_tf32(oacc[2 * nfp],     a, bfr);
                mma_tf32(oacc[2 * nfp + 1], a, bfr + 2);
            }
        }
        __syncwarp();
    }

    // epilogue
    float il0 = 1.0f / l0r, il1 = 1.0f / l1r;
    const int r0 = q0 + wr + g, r1 = r0 + 8;
#pragma unroll
    for (int nf = 0; nf < 16; nf++) {
        int c = nf * 8 + 2 * tg;
        yb[(size_t)r0 * C_SZ + c]     = oacc[nf][0] * il0;
        yb[(size_t)r0 * C_SZ + c + 1] = oacc[nf][1] * il0;
        yb[(size_t)r1 * C_SZ + c]     = oacc[nf][2] * il1;
        yb[(size_t)r1 * C_SZ + c + 1] = oacc[nf][3] * il1;
    }
}

// ---------------------------------------------------------------------------
// Launch
// ---------------------------------------------------------------------------
extern "C" void kernel_launch(void* const* d_in, const int* in_sizes, int n_in,
                              void* d_out, int out_size) {
    const float* x  = (const float*)d_in[0];
    const float* Wq = (const float*)d_in[1];
    const float* Wk = (const float*)d_in[2];
    const float* Wv = (const float*)d_in[3];
    const float* Wo = (const float*)d_in[4];
    float* out = (float*)d_out;

    float *gq, *gk, *gvt, *gy;
    cudaGetSymbolAddress((void**)&gq, g_q);
    cudaGetSymbolAddress((void**)&gk, g_k);
    cudaGetSymbolAddress((void**)&gvt, g_vt);
    cudaGetSymbolAddress((void**)&gy, g_y);

    cudaFuncSetAttribute(attn_kernel,
                         cudaFuncAttributeMaxDynamicSharedMemorySize,
                         ATTN_SMEM_BYTES);
    cudaFuncSetAttribute(gemm_nt,
                         cudaFuncAttributeMaxDynamicSharedMemorySize,
                         GEMM_SMEM_BYTES);

    init_invf<<<1, 64>>>();
    init_cs<<<T_SZ, 64>>>();

    // Q projection: 256x128 tiles
    gemm_nt<<<dim3(C_SZ / BN, MROWS / BM, 1), 256, GEMM_SMEM_BYTES>>>(
        x, Wq, Wq, gq, gq, C_SZ, C_SZ, 0);
    // K + V projections fused (z=0: K normal; z=1: V transposed epilogue)
    gemm_nt<<<dim3(KVD / BN, MROWS / BM, 2), 256, GEMM_SMEM_BYTES>>>(
        x, Wk, Wv, gk, gvt, KVD, C_SZ, MROWS);

    // RMSNorm + RoPE on q, k
    {
        int total_warps = MROWS * NH + MROWS * NKV;
        int blocks = (total_warps + 7) / 8;
        normrope<<<blocks, 256>>>(gq, gk);
    }

    // Flash attention
    attn_kernel<<<dim3(T_SZ / 128, NH, B_SZ), 256, ATTN_SMEM_BYTES>>>(gq, gk, gvt, gy);

    // Output projection
    gemm_nt<<<dim3(C_SZ / BN, MROWS / BM, 1), 256, GEMM_SMEM_BYTES>>>(
        gy, Wo, Wo, out, out, C_SZ, C_SZ, 0);
}